// round 1
// baseline (speedup 1.0000x reference)
#include <cuda_runtime.h>
#include <math.h>

// Problem constants
#define NN    512           // sequence length
#define CS    384           // C_S
#define CZ    128           // C_Z
#define HH    12            // heads
#define CH    16            // C_H
#define PQN   4             // query points
#define PVN   8             // value points
#define DQK   (HH*CH)       // 192
#define DQP   (HH*PQN*3)    // 144
#define DVP   (HH*PVN*3)    // 288
#define FH    (CH + PVN*3 + PVN + CZ)  // 176 per-head feature width
#define FEAT  (HH*FH)       // 2112
#define COUT  384

// ---------------- scratch (device globals; no allocation allowed) ----------
__device__ __align__(16) float g_q  [NN*DQK];
__device__ __align__(16) float g_k  [NN*DQK];
__device__ __align__(16) float g_v  [NN*DQK];
__device__ __align__(16) float g_qpg[NN*DQP];
__device__ __align__(16) float g_kpg[NN*DQP];
__device__ __align__(16) float g_vpg[NN*DVP];
__device__ __align__(16) float g_feat[NN*FEAT];

// ---------------- kernel 1: plain linear  out[n,o] = s[n,:]@w[:,o]+b[o] ----
__global__ void linear_kernel(const float* __restrict__ s,
                              const float* __restrict__ w,
                              const float* __restrict__ b,
                              float* __restrict__ out, int Dout) {
    int n = blockIdx.x;
    __shared__ float srow[CS];
    for (int i = threadIdx.x; i < CS; i += blockDim.x) srow[i] = s[n*CS + i];
    __syncthreads();
    for (int o = threadIdx.x; o < Dout; o += blockDim.x) {
        float acc = b[o];
        #pragma unroll 4
        for (int c = 0; c < CS; c++) acc += srow[c] * w[c*Dout + o];
        out[n*Dout + o] = acc;
    }
}

// ---------------- kernel 2: point projection + frame rotation -------------
// outg[n, h*P*3 + p*3 + i] = sum_j rot[n,i,j] * (s@w+b)[n,h,p,j] + t[n,i]
__global__ void point_proj_kernel(const float* __restrict__ s,
                                  const float* __restrict__ w,
                                  const float* __restrict__ b,
                                  const float* __restrict__ rot,
                                  const float* __restrict__ trans,
                                  float* __restrict__ outg, int P) {
    int n = blockIdx.x;
    int Dout = HH * P * 3;
    __shared__ float srow[CS];
    __shared__ float R[9];
    __shared__ float T[3];
    if (threadIdx.x < 9) R[threadIdx.x] = rot[n*9 + threadIdx.x];
    if (threadIdx.x < 3) T[threadIdx.x] = trans[n*3 + threadIdx.x];
    for (int i = threadIdx.x; i < CS; i += blockDim.x) srow[i] = s[n*CS + i];
    __syncthreads();
    for (int hp = threadIdx.x; hp < HH*P; hp += blockDim.x) {
        float l0 = b[hp*3+0], l1 = b[hp*3+1], l2 = b[hp*3+2];
        for (int c = 0; c < CS; c++) {
            float sv = srow[c];
            const float* wr = w + (size_t)c*Dout + hp*3;
            l0 += sv*wr[0]; l1 += sv*wr[1]; l2 += sv*wr[2];
        }
        float gx = R[0]*l0 + R[1]*l1 + R[2]*l2 + T[0];
        float gy = R[3]*l0 + R[4]*l1 + R[5]*l2 + T[1];
        float gz = R[6]*l0 + R[7]*l1 + R[8]*l2 + T[2];
        outg[n*Dout + hp*3 + 0] = gx;
        outg[n*Dout + hp*3 + 1] = gy;
        outg[n*Dout + hp*3 + 2] = gz;
    }
}

// ---------------- kernel 3: fused attention per query row n ---------------
// grid = 512 blocks (one per n), blockDim = 384 = TM*H
#define TM 32
#define WB_STRIDE 132   // padded per-head wb row to limit smem bank conflicts

// smem layout (floats):
#define OFF_Q     0                          // 192
#define OFF_QPG   (OFF_Q + 192)              // 144
#define OFF_WB    (OFF_QPG + 144)            // 12*132 = 1584 (transposed, padded)
#define OFF_BB    (OFF_WB + HH*WB_STRIDE)    // 12
#define OFF_LOG   (OFF_BB + 12)              // 512*12 = 6144
#define OFF_ACC   (OFF_LOG + NN*HH)          // 12*168 = 2016
#define OFF_TILE  (OFF_ACC + HH*168)         // 19456 (max of pass1/pass2 tile)
#define OFF_DN    (OFF_TILE + 19456)         // 12
#define OFF_R     (OFF_DN + 12)              // 9
#define OFF_T     (OFF_R + 9)                // 3
#define SMEM_FLOATS (OFF_T + 3)
#define SMEM_BYTES  (SMEM_FLOATS * 4)

__global__ void attn_kernel(const float* __restrict__ z,
                            const float* __restrict__ trans,
                            const float* __restrict__ rot,
                            const int*   __restrict__ mask,
                            const float* __restrict__ wb,
                            const float* __restrict__ bb) {
    extern __shared__ float sm[];
    float* q_s   = sm + OFF_Q;
    float* qpg_s = sm + OFF_QPG;
    float* wb_s  = sm + OFF_WB;
    float* bb_s  = sm + OFF_BB;
    float* logits = sm + OFF_LOG;
    float* acc   = sm + OFF_ACC;
    float* tile  = sm + OFF_TILE;
    float* dn    = sm + OFF_DN;
    float* R     = sm + OFF_R;
    float* T     = sm + OFF_T;

    int n   = blockIdx.x;
    int tid = threadIdx.x;

    for (int i = tid; i < 192; i += 384) q_s[i]   = g_q[n*192 + i];
    for (int i = tid; i < 144; i += 384) qpg_s[i] = g_qpg[n*144 + i];
    // wb is [c][h] (128x12) global; store transposed+padded [h][c]
    for (int i = tid; i < CZ*HH; i += 384) {
        int c = i / HH, h = i % HH;
        wb_s[h*WB_STRIDE + c] = wb[i];
    }
    if (tid < 12) bb_s[tid] = bb[tid];
    if (tid < 9)  R[tid] = rot[n*9 + tid];
    if (tid < 3)  T[tid] = trans[n*3 + tid];
    int mask_n = mask[n];
    __syncthreads();

    // ---------------- pass 1: logits -------------------------------------
    for (int m0 = 0; m0 < NN; m0 += TM) {
        // contiguous tile copies: k [32*192], kpg [32*144], z [32*128]
        float4*       kt  = (float4*)(tile);
        float4*       kpt = (float4*)(tile + TM*192);
        float4*       zt  = (float4*)(tile + TM*192 + TM*144);
        const float4* gk  = (const float4*)(g_k   + m0*192);
        const float4* gkp = (const float4*)(g_kpg + m0*144);
        const float4* gz  = (const float4*)(z + ((size_t)n*NN + m0)*CZ);
        for (int i = tid; i < TM*192/4; i += 384) kt[i]  = gk[i];
        for (int i = tid; i < TM*144/4; i += 384) kpt[i] = gkp[i];
        for (int i = tid; i < TM*128/4; i += 384) zt[i]  = gz[i];
        __syncthreads();

        {
            int p  = tid;           // 384 pairs == blockDim
            int ml = p / HH;
            int h  = p % HH;
            // scalar qk
            const float* kr = tile + ml*192 + h*CH;
            const float* qr = q_s + h*CH;
            float sc = 0.f;
            #pragma unroll
            for (int c = 0; c < CH; c++) sc += qr[c]*kr[c];
            float logit = sc * 0.25f;   // 1/sqrt(16)
            // point term
            const float* kpr = tile + TM*192 + ml*144 + h*12;
            const float* qpr = qpg_s + h*12;
            float ss = 0.f;
            #pragma unroll
            for (int c = 0; c < 12; c++) { float d = qpr[c]-kpr[c]; ss += d*d; }
            logit -= 0.5f * ss;
            // pair bias: z[n,m,:] @ wb[:,h] + bb[h]
            const float4* zr4 = (const float4*)(tile + TM*192 + TM*144 + ml*CZ);
            const float4* wr4 = (const float4*)(wb_s + h*WB_STRIDE);
            float bz = bb_s[h];
            #pragma unroll
            for (int c4 = 0; c4 < CZ/4; c4++) {
                float4 zv = zr4[c4], wv = wr4[c4];
                bz += zv.x*wv.x + zv.y*wv.y + zv.z*wv.z + zv.w*wv.w;
            }
            logit += bz;
            int m = m0 + ml;
            if (mask_n == 0 || mask[m] == 0) logit = -1e30f;
            logits[m*HH + h] = logit;
        }
        __syncthreads();
    }

    // ---------------- softmax stats: one warp per head --------------------
    {
        int w = tid >> 5, lane = tid & 31;   // w in [0,12)
        float mx = -1e30f;
        for (int m = lane; m < NN; m += 32) mx = fmaxf(mx, logits[m*HH + w]);
        #pragma unroll
        for (int o = 16; o; o >>= 1) mx = fmaxf(mx, __shfl_xor_sync(0xffffffffu, mx, o));
        float s = 0.f;
        for (int m = lane; m < NN; m += 32) {
            float e = __expf(logits[m*HH + w] - mx);
            logits[m*HH + w] = e;
            s += e;
        }
        #pragma unroll
        for (int o = 16; o; o >>= 1) s += __shfl_xor_sync(0xffffffffu, s, o);
        if (lane == 0) dn[w] = s;
    }
    // zero accumulators
    for (int i = tid; i < HH*168; i += 384) acc[i] = 0.f;
    __syncthreads();

    // ---------------- pass 2: weighted sums -------------------------------
    for (int m0 = 0; m0 < NN; m0 += TM) {
        float4*       vt  = (float4*)(tile);                       // 32*192
        float4*       vpt = (float4*)(tile + TM*192);              // 32*288
        float4*       zt  = (float4*)(tile + TM*192 + TM*288);     // 32*128
        const float4* gv  = (const float4*)(g_v   + m0*192);
        const float4* gvp = (const float4*)(g_vpg + m0*288);
        const float4* gz  = (const float4*)(z + ((size_t)n*NN + m0)*CZ);
        for (int i = tid; i < TM*192/4; i += 384) vt[i]  = gv[i];
        for (int i = tid; i < TM*288/4; i += 384) vpt[i] = gvp[i];
        for (int i = tid; i < TM*128/4; i += 384) zt[i]  = gz[i];
        __syncthreads();

        for (int s_ = tid; s_ < HH*168; s_ += 384) {
            int h = s_ / 168, j = s_ % 168;
            const float* xptr;
            int stride;
            if (j < 16)       { xptr = tile + h*CH + j;                       stride = 192; }
            else if (j < 40)  { xptr = tile + TM*192 + h*24 + (j-16);         stride = 288; }
            else              { xptr = tile + TM*192 + TM*288 + (j-40);       stride = 128; }
            const float* wrow = logits + m0*HH + h;
            float a = 0.f;
            #pragma unroll 8
            for (int ml = 0; ml < TM; ml++) a += wrow[ml*HH] * xptr[ml*stride];
            acc[s_] += a;
        }
        __syncthreads();
    }

    // ---------------- finalize -------------------------------------------
    // scalar (j<16) and pair (j>=40) features
    for (int s_ = tid; s_ < HH*168; s_ += 384) {
        int h = s_ / 168, j = s_ % 168;
        float val = acc[s_] / dn[h];
        if (j < 16)       g_feat[n*FEAT + h*FH + j] = val;
        else if (j >= 40) g_feat[n*FEAT + h*FH + 48 + (j-40)] = val;
    }
    // points: back to local frame + norms
    if (tid < HH*PVN) {
        int h = tid / PVN, p = tid % PVN;
        float inv = 1.f / dn[h];
        float x0 = acc[h*168 + 16 + p*3 + 0]*inv - T[0];
        float x1 = acc[h*168 + 16 + p*3 + 1]*inv - T[1];
        float x2 = acc[h*168 + 16 + p*3 + 2]*inv - T[2];
        // local = rot^T @ x
        float l0 = R[0]*x0 + R[3]*x1 + R[6]*x2;
        float l1 = R[1]*x0 + R[4]*x1 + R[7]*x2;
        float l2 = R[2]*x0 + R[5]*x1 + R[8]*x2;
        g_feat[n*FEAT + h*FH + 16 + p*3 + 0] = l0;
        g_feat[n*FEAT + h*FH + 16 + p*3 + 1] = l1;
        g_feat[n*FEAT + h*FH + 16 + p*3 + 2] = l2;
        g_feat[n*FEAT + h*FH + 40 + p] = sqrtf(l0*l0 + l1*l1 + l2*l2);
    }
}

// ---------------- kernel 4: output projection -----------------------------
// 8 query rows per block so wo traffic through L2 is 64x, not 512x.
#define ROWS_PER_BLK 8
#define KCHUNK 528          // 2112 = 4*528
__global__ void out_kernel(const float* __restrict__ wo,
                           const float* __restrict__ bo,
                           float* __restrict__ out) {
    int n0 = blockIdx.x * ROWS_PER_BLK;
    __shared__ float f[ROWS_PER_BLK][KCHUNK];
    int o = threadIdx.x;   // 384 threads
    float a[ROWS_PER_BLK];
    #pragma unroll
    for (int r = 0; r < ROWS_PER_BLK; r++) a[r] = bo[o];
    for (int k0 = 0; k0 < FEAT; k0 += KCHUNK) {
        for (int i = threadIdx.x; i < ROWS_PER_BLK*KCHUNK; i += blockDim.x) {
            int r = i / KCHUNK, kk = i % KCHUNK;
            f[r][kk] = g_feat[(size_t)(n0 + r)*FEAT + k0 + kk];
        }
        __syncthreads();
        for (int kk = 0; kk < KCHUNK; kk++) {
            float wv = wo[(size_t)(k0 + kk)*COUT + o];
            #pragma unroll
            for (int r = 0; r < ROWS_PER_BLK; r++) a[r] += f[r][kk] * wv;
        }
        __syncthreads();
    }
    #pragma unroll
    for (int r = 0; r < ROWS_PER_BLK; r++) out[(size_t)(n0 + r)*COUT + o] = a[r];
}

// ---------------- launch ---------------------------------------------------
extern "C" void kernel_launch(void* const* d_in, const int* in_sizes, int n_in,
                              void* d_out, int out_size) {
    const float* s     = (const float*)d_in[0];
    const float* z     = (const float*)d_in[1];
    const float* trans = (const float*)d_in[2];
    const float* rot   = (const float*)d_in[3];
    const int*   mask  = (const int*)  d_in[4];
    const float* wq    = (const float*)d_in[5];
    const float* bq    = (const float*)d_in[6];
    const float* wk    = (const float*)d_in[7];
    const float* bk    = (const float*)d_in[8];
    const float* wv    = (const float*)d_in[9];
    const float* bv    = (const float*)d_in[10];
    const float* wqp   = (const float*)d_in[11];
    const float* bqp   = (const float*)d_in[12];
    const float* wkp   = (const float*)d_in[13];
    const float* bkp   = (const float*)d_in[14];
    const float* wvp   = (const float*)d_in[15];
    const float* bvp   = (const float*)d_in[16];
    const float* wb    = (const float*)d_in[17];
    const float* bb    = (const float*)d_in[18];
    const float* wo    = (const float*)d_in[19];
    const float* bo    = (const float*)d_in[20];
    float* out = (float*)d_out;

    cudaFuncSetAttribute(attn_kernel,
                         cudaFuncAttributeMaxDynamicSharedMemorySize, SMEM_BYTES);

    float* d_q   = nullptr; cudaGetSymbolAddress((void**)&d_q,   g_q);
    float* d_k   = nullptr; cudaGetSymbolAddress((void**)&d_k,   g_k);
    float* d_v   = nullptr; cudaGetSymbolAddress((void**)&d_v,   g_v);
    float* d_qpg = nullptr; cudaGetSymbolAddress((void**)&d_qpg, g_qpg);
    float* d_kpg = nullptr; cudaGetSymbolAddress((void**)&d_kpg, g_kpg);
    float* d_vpg = nullptr; cudaGetSymbolAddress((void**)&d_vpg, g_vpg);

    linear_kernel<<<NN, 192>>>(s, wq, bq, d_q, DQK);
    linear_kernel<<<NN, 192>>>(s, wk, bk, d_k, DQK);
    linear_kernel<<<NN, 192>>>(s, wv, bv, d_v, DQK);
    point_proj_kernel<<<NN, 128>>>(s, wqp, bqp, rot, trans, d_qpg, PQN);
    point_proj_kernel<<<NN, 128>>>(s, wkp, bkp, rot, trans, d_kpg, PQN);
    point_proj_kernel<<<NN, 128>>>(s, wvp, bvp, rot, trans, d_vpg, PVN);

    attn_kernel<<<NN, 384, SMEM_BYTES>>>(z, trans, rot, mask, wb, bb);

    out_kernel<<<NN / ROWS_PER_BLK, COUT>>>(wo, bo, out);
}

// round 5
// speedup vs baseline: 1.4622x; 1.4622x over previous
#include <cuda_runtime.h>
#include <math.h>

// Problem constants
#define NN    512
#define CS    384
#define CZ    128
#define HH    12
#define CH    16
#define PQN   4
#define PVN   8
#define DPROJ 1152          // 192*3 + 144*2 + 288 concatenated
#define FH    (CH + PVN*3 + PVN + CZ)  // 176
#define FEAT  (HH*FH)       // 2112
#define COUT  384

// segment bases inside g_proj row
#define OFF_PQ_Q   0
#define OFF_PQ_K   192
#define OFF_PQ_V   384
#define OFF_PQ_QP  576
#define OFF_PQ_KP  720
#define OFF_PQ_VP  864

// ---------------- scratch ----------------
__device__ __align__(16) float g_proj[NN*DPROJ];
__device__ __align__(16) float g_qpg [NN*HH*PQN*3];
__device__ __align__(16) float g_kpg [NN*HH*PQN*3];
__device__ __align__(16) float g_vpg [NN*HH*PVN*3];
__device__ __align__(16) float g_feat[NN*FEAT];

// =================== fused projection SGEMM ===========================
// C[n, seg_base+col] = s[n,:]@W_seg[:,col] + b_seg[col]
// tiles: 64 rows x 48 cols, K-chunk 32, 256 threads, 4x3 micro-tile
#define GT_M 64
#define GT_N 48
#define GT_K 32
__global__ void proj_gemm_kernel(const float* __restrict__ s,
    const float* __restrict__ wq,  const float* __restrict__ bq,
    const float* __restrict__ wk,  const float* __restrict__ bk,
    const float* __restrict__ wv,  const float* __restrict__ bv,
    const float* __restrict__ wqp, const float* __restrict__ bqp,
    const float* __restrict__ wkp, const float* __restrict__ bkp,
    const float* __restrict__ wvp, const float* __restrict__ bvp) {
    // decode column tile -> segment
    int bt = blockIdx.y;
    const float *W, *B; int Dout, base, t;
    if      (bt < 4)  { W=wq;  B=bq;  Dout=192; base=OFF_PQ_Q;  t=bt; }
    else if (bt < 8)  { W=wk;  B=bk;  Dout=192; base=OFF_PQ_K;  t=bt-4; }
    else if (bt < 12) { W=wv;  B=bv;  Dout=192; base=OFF_PQ_V;  t=bt-8; }
    else if (bt < 15) { W=wqp; B=bqp; Dout=144; base=OFF_PQ_QP; t=bt-12; }
    else if (bt < 18) { W=wkp; B=bkp; Dout=144; base=OFF_PQ_KP; t=bt-15; }
    else              { W=wvp; B=bvp; Dout=288; base=OFF_PQ_VP; t=bt-18; }
    int col0 = t*GT_N;
    int n0   = blockIdx.x*GT_M;

    __shared__ float sA[GT_K][GT_M+1];
    __shared__ float sB[GT_K][GT_N];
    int tid = threadIdx.x;
    int tx = tid & 15, ty = tid >> 4;
    float acc[4][3] = {};

    for (int k0 = 0; k0 < CS; k0 += GT_K) {
        for (int i = tid; i < GT_M*GT_K; i += 256) {
            int m = i >> 5, k = i & 31;
            sA[k][m] = s[(size_t)(n0+m)*CS + k0 + k];
        }
        for (int i = tid; i < GT_K*GT_N; i += 256) {
            int k = i / GT_N, c = i % GT_N;
            sB[k][c] = W[(size_t)(k0+k)*Dout + col0 + c];
        }
        __syncthreads();
        #pragma unroll
        for (int kk = 0; kk < GT_K; kk++) {
            float a[4], b[3];
            #pragma unroll
            for (int r = 0; r < 4; r++) a[r] = sA[kk][ty + 16*r];
            #pragma unroll
            for (int c = 0; c < 3; c++) b[c] = sB[kk][tx + 16*c];
            #pragma unroll
            for (int r = 0; r < 4; r++)
                #pragma unroll
                for (int c = 0; c < 3; c++) acc[r][c] += a[r]*b[c];
        }
        __syncthreads();
    }
    #pragma unroll
    for (int c = 0; c < 3; c++) {
        float bb_ = B[col0 + tx + 16*c];
        #pragma unroll
        for (int r = 0; r < 4; r++)
            g_proj[(size_t)(n0+ty+16*r)*DPROJ + base + col0 + tx + 16*c] = acc[r][c] + bb_;
    }
}

// =================== rotation epilogue for point projections ==========
// 192 threads: 48 qp + 48 kp + 96 vp (h,p) triples
__global__ void rotate_points_kernel(const float* __restrict__ rot,
                                     const float* __restrict__ trans) {
    int n = blockIdx.x, t = threadIdx.x;
    __shared__ float R[9], T[3];
    if (t < 9) R[t] = rot[n*9 + t];
    if (t < 3) T[t] = trans[n*3 + t];
    __syncthreads();
    int src_off, hp; float* dst;
    if      (t < 48)  { hp = t;      src_off = OFF_PQ_QP; dst = g_qpg + n*144; }
    else if (t < 96)  { hp = t-48;   src_off = OFF_PQ_KP; dst = g_kpg + n*144; }
    else              { hp = t-96;   src_off = OFF_PQ_VP; dst = g_vpg + n*288; }
    const float* l = g_proj + (size_t)n*DPROJ + src_off + hp*3;
    float l0=l[0], l1=l[1], l2=l[2];
    dst[hp*3+0] = R[0]*l0 + R[1]*l1 + R[2]*l2 + T[0];
    dst[hp*3+1] = R[3]*l0 + R[4]*l1 + R[5]*l2 + T[1];
    dst[hp*3+2] = R[6]*l0 + R[7]*l1 + R[8]*l2 + T[2];
}

// =================== fused attention per query row ====================
#define TM1 32          // pass-1 m-tile
#define TM2 16          // pass-2 m-tile
#define WB_STRIDE 132

#define OFF_Q     0                          // 192
#define OFF_QPG   (OFF_Q + 192)              // 144
#define OFF_WB    (OFF_QPG + 144)            // 1584
#define OFF_BB    (OFF_WB + HH*WB_STRIDE)    // 12
#define OFF_LOG   (OFF_BB + 12)              // 6144
#define OFF_ACC   (OFF_LOG + NN*HH)          // 2016
#define OFF_DN    (OFF_ACC + HH*168)         // 12
#define OFF_R     (OFF_DN + 12)              // 9
#define OFF_T     (OFF_R + 9)                // 3
#define OFF_TILE  (OFF_T + 3)                // 14848
#define TILE_FLOATS 14848                    // max(32*464, 16*608)
#define SMEM_FLOATS (OFF_TILE + TILE_FLOATS)
#define SMEM_BYTES  (SMEM_FLOATS * 4)

__global__ void attn_kernel(const float* __restrict__ z,
                            const float* __restrict__ trans,
                            const float* __restrict__ rot,
                            const int*   __restrict__ mask,
                            const float* __restrict__ wb,
                            const float* __restrict__ bb) {
    extern __shared__ float sm[];
    float* q_s    = sm + OFF_Q;
    float* qpg_s  = sm + OFF_QPG;
    float* wb_s   = sm + OFF_WB;
    float* bb_s   = sm + OFF_BB;
    float* logits = sm + OFF_LOG;
    float* acc    = sm + OFF_ACC;
    float* dn     = sm + OFF_DN;
    float* R      = sm + OFF_R;
    float* T      = sm + OFF_T;
    float* tile   = sm + OFF_TILE;

    int n = blockIdx.x, tid = threadIdx.x;

    for (int i = tid; i < 192; i += 384) q_s[i]   = g_proj[(size_t)n*DPROJ + i];
    for (int i = tid; i < 144; i += 384) qpg_s[i] = g_qpg[n*144 + i];
    for (int i = tid; i < CZ*HH; i += 384) {
        int c = i / HH, h = i % HH;
        wb_s[h*WB_STRIDE + c] = wb[i];
    }
    if (tid < 12) bb_s[tid] = bb[tid];
    if (tid < 9)  R[tid] = rot[n*9 + tid];
    if (tid < 3)  T[tid] = trans[n*3 + tid];
    int mask_n = mask[n];
    __syncthreads();

    // ---------------- pass 1: logits ------------------------------------
    const int ml = tid / HH;       // 0..31
    const int h1 = tid % HH;
    for (int m0 = 0; m0 < NN; m0 += TM1) {
        float4* kt  = (float4*)(tile);                        // 32*192
        float4* kpt = (float4*)(tile + TM1*192);              // 32*144
        float4* zt  = (float4*)(tile + TM1*(192+144));        // 32*128
        for (int i = tid; i < TM1*48; i += 384) {
            int r = i / 48, c = i % 48;
            kt[i] = ((const float4*)(g_proj + (size_t)(m0+r)*DPROJ + OFF_PQ_K))[c];
        }
        {
            const float4* gkp = (const float4*)(g_kpg + m0*144);
            for (int i = tid; i < TM1*36; i += 384) kpt[i] = gkp[i];
            const float4* gz = (const float4*)(z + ((size_t)n*NN + m0)*CZ);
            for (int i = tid; i < TM1*32; i += 384) zt[i] = gz[i];
        }
        __syncthreads();
        {
            const float4* kr4  = (const float4*)(tile + ml*192 + h1*CH);
            const float4* qr4  = (const float4*)(q_s + h1*CH);
            float sc = 0.f;
            #pragma unroll
            for (int c = 0; c < 4; c++) {
                float4 a = qr4[c], b = kr4[c];
                sc += a.x*b.x + a.y*b.y + a.z*b.z + a.w*b.w;
            }
            float logit = sc * 0.25f;
            const float4* kp4 = (const float4*)(tile + TM1*192 + ml*144 + h1*12);
            const float4* qp4 = (const float4*)(qpg_s + h1*12);
            float ss = 0.f;
            #pragma unroll
            for (int c = 0; c < 3; c++) {
                float4 a = qp4[c], b = kp4[c];
                float dx=a.x-b.x, dy=a.y-b.y, dz=a.z-b.z, dw=a.w-b.w;
                ss += dx*dx + dy*dy + dz*dz + dw*dw;
            }
            logit -= 0.5f * ss;
            const float4* zr4 = (const float4*)(tile + TM1*(192+144) + ml*CZ);
            const float4* wr4 = (const float4*)(wb_s + h1*WB_STRIDE);
            float bz = bb_s[h1];
            #pragma unroll
            for (int c4 = 0; c4 < CZ/4; c4++) {
                float4 zv = zr4[c4], wv = wr4[c4];
                bz += zv.x*wv.x + zv.y*wv.y + zv.z*wv.z + zv.w*wv.w;
            }
            logit += bz;
            int m = m0 + ml;
            if (mask_n == 0 || mask[m] == 0) logit = -1e30f;
            logits[m*HH + h1] = logit;
        }
        __syncthreads();
    }

    // ---------------- softmax: one warp per head --------------------------
    {
        int w = tid >> 5, lane = tid & 31;
        float mx = -1e30f;
        for (int m = lane; m < NN; m += 32) mx = fmaxf(mx, logits[m*HH + w]);
        #pragma unroll
        for (int o = 16; o; o >>= 1) mx = fmaxf(mx, __shfl_xor_sync(0xffffffffu, mx, o));
        float s = 0.f;
        for (int m = lane; m < NN; m += 32) {
            float e = __expf(logits[m*HH + w] - mx);
            logits[m*HH + w] = e;
            s += e;
        }
        #pragma unroll
        for (int o = 16; o; o >>= 1) s += __shfl_xor_sync(0xffffffffu, s, o);
        if (lane == 0) dn[w] = s;
    }
    __syncthreads();

    // ---------------- pass 2: weighted sums (register-accumulated) --------
    // 504 float4 groups: h in [0,12), g in [0,42), j = g*4 over 168 outputs
    int s0 = tid, s1 = tid + 384;
    bool has1 = (s1 < HH*42);
    int h0 = s0/42, g0 = s0%42, j0 = g0*4;
    int h1b = has1 ? s1/42 : 0, g1 = has1 ? s1%42 : 0, j1 = g1*4;

    const float* x0; int st0;
    if (j0 < 16)      { x0 = tile + h0*CH + j0;                    st0 = 192; }
    else if (j0 < 40) { x0 = tile + TM2*192 + h0*24 + (j0-16);     st0 = 288; }
    else              { x0 = tile + TM2*(192+288) + (j0-40);       st0 = 128; }
    const float* x1 = tile; int st1 = 192;
    if (has1) {
        if (j1 < 16)      { x1 = tile + h1b*CH + j1;                  st1 = 192; }
        else if (j1 < 40) { x1 = tile + TM2*192 + h1b*24 + (j1-16);   st1 = 288; }
        else              { x1 = tile + TM2*(192+288) + (j1-40);      st1 = 128; }
    }
    float4 a0 = {0,0,0,0}, a1 = {0,0,0,0};

    for (int m0 = 0; m0 < NN; m0 += TM2) {
        float4* vt  = (float4*)(tile);                      // 16*192
        float4* vpt = (float4*)(tile + TM2*192);            // 16*288
        float4* zt  = (float4*)(tile + TM2*(192+288));      // 16*128
        for (int i = tid; i < TM2*48; i += 384) {
            int r = i / 48, c = i % 48;
            vt[i] = ((const float4*)(g_proj + (size_t)(m0+r)*DPROJ + OFF_PQ_V))[c];
        }
        {
            const float4* gvp = (const float4*)(g_vpg + m0*288);
            for (int i = tid; i < TM2*72; i += 384) vpt[i] = gvp[i];
            const float4* gz = (const float4*)(z + ((size_t)n*NN + m0)*CZ);
            for (int i = tid; i < TM2*32; i += 384) zt[i] = gz[i];
        }
        __syncthreads();
        const float* w0r = logits + m0*HH + h0;
        const float* w1r = logits + m0*HH + h1b;
        #pragma unroll 8
        for (int mm = 0; mm < TM2; mm++) {
            float w0v = w0r[mm*HH];
            float4 xv = *(const float4*)(x0 + mm*st0);
            a0.x += w0v*xv.x; a0.y += w0v*xv.y; a0.z += w0v*xv.z; a0.w += w0v*xv.w;
            if (has1) {
                float w1v = w1r[mm*HH];
                float4 yv = *(const float4*)(x1 + mm*st1);
                a1.x += w1v*yv.x; a1.y += w1v*yv.y; a1.z += w1v*yv.z; a1.w += w1v*yv.w;
            }
        }
        __syncthreads();
    }
    *(float4*)(acc + h0*168 + j0) = a0;
    if (has1) *(float4*)(acc + h1b*168 + j1) = a1;
    __syncthreads();

    // ---------------- finalize -------------------------------------------
    for (int s_ = tid; s_ < HH*168; s_ += 384) {
        int h = s_/168, j = s_%168;
        float val = acc[s_] / dn[h];
        if (j < 16)       g_feat[(size_t)n*FEAT + h*FH + j] = val;
        else if (j >= 40) g_feat[(size_t)n*FEAT + h*FH + 48 + (j-40)] = val;
    }
    if (tid < HH*PVN) {
        int h = tid / PVN, p = tid % PVN;
        float inv = 1.f / dn[h];
        float x0_ = acc[h*168 + 16 + p*3 + 0]*inv - T[0];
        float x1_ = acc[h*168 + 16 + p*3 + 1]*inv - T[1];
        float x2_ = acc[h*168 + 16 + p*3 + 2]*inv - T[2];
        float l0 = R[0]*x0_ + R[3]*x1_ + R[6]*x2_;
        float l1 = R[1]*x0_ + R[4]*x1_ + R[7]*x2_;
        float l2 = R[2]*x0_ + R[5]*x1_ + R[8]*x2_;
        g_feat[(size_t)n*FEAT + h*FH + 16 + p*3 + 0] = l0;
        g_feat[(size_t)n*FEAT + h*FH + 16 + p*3 + 1] = l1;
        g_feat[(size_t)n*FEAT + h*FH + 16 + p*3 + 2] = l2;
        g_feat[(size_t)n*FEAT + h*FH + 40 + p] = sqrtf(l0*l0 + l1*l1 + l2*l2);
    }
}

// =================== output projection SGEMM ==========================
// out[n, o] = g_feat[n,:]@wo[:,o] + bo[o];  512x384x2112
__global__ void out_gemm_kernel(const float* __restrict__ wo,
                                const float* __restrict__ bo,
                                float* __restrict__ out) {
    int n0 = blockIdx.x*GT_M;
    int col0 = blockIdx.y*GT_N;
    __shared__ float sA[GT_K][GT_M+1];
    __shared__ float sB[GT_K][GT_N];
    int tid = threadIdx.x;
    int tx = tid & 15, ty = tid >> 4;
    float acc[4][3] = {};
    for (int k0 = 0; k0 < FEAT; k0 += GT_K) {
        for (int i = tid; i < GT_M*GT_K; i += 256) {
            int m = i >> 5, k = i & 31;
            sA[k][m] = g_feat[(size_t)(n0+m)*FEAT + k0 + k];
        }
        for (int i = tid; i < GT_K*GT_N; i += 256) {
            int k = i / GT_N, c = i % GT_N;
            sB[k][c] = wo[(size_t)(k0+k)*COUT + col0 + c];
        }
        __syncthreads();
        #pragma unroll
        for (int kk = 0; kk < GT_K; kk++) {
            float a[4], b[3];
            #pragma unroll
            for (int r = 0; r < 4; r++) a[r] = sA[kk][ty + 16*r];
            #pragma unroll
            for (int c = 0; c < 3; c++) b[c] = sB[kk][tx + 16*c];
            #pragma unroll
            for (int r = 0; r < 4; r++)
                #pragma unroll
                for (int c = 0; c < 3; c++) acc[r][c] += a[r]*b[c];
        }
        __syncthreads();
    }
    #pragma unroll
    for (int c = 0; c < 3; c++) {
        float bb_ = bo[col0 + tx + 16*c];
        #pragma unroll
        for (int r = 0; r < 4; r++)
            out[(size_t)(n0+ty+16*r)*COUT + col0 + tx + 16*c] = acc[r][c] + bb_;
    }
}

// ---------------- launch ---------------------------------------------------
extern "C" void kernel_launch(void* const* d_in, const int* in_sizes, int n_in,
                              void* d_out, int out_size) {
    const float* s     = (const float*)d_in[0];
    const float* z     = (const float*)d_in[1];
    const float* trans = (const float*)d_in[2];
    const float* rot   = (const float*)d_in[3];
    const int*   mask  = (const int*)  d_in[4];
    const float* wq    = (const float*)d_in[5];
    const float* bq    = (const float*)d_in[6];
    const float* wk    = (const float*)d_in[7];
    const float* bk    = (const float*)d_in[8];
    const float* wv    = (const float*)d_in[9];
    const float* bv    = (const float*)d_in[10];
    const float* wqp   = (const float*)d_in[11];
    const float* bqp   = (const float*)d_in[12];
    const float* wkp   = (const float*)d_in[13];
    const float* bkp   = (const float*)d_in[14];
    const float* wvp   = (const float*)d_in[15];
    const float* bvp   = (const float*)d_in[16];
    const float* wb    = (const float*)d_in[17];
    const float* bb    = (const float*)d_in[18];
    const float* wo    = (const float*)d_in[19];
    const float* bo    = (const float*)d_in[20];
    float* out = (float*)d_out;

    cudaFuncSetAttribute(attn_kernel,
                         cudaFuncAttributeMaxDynamicSharedMemorySize, SMEM_BYTES);

    proj_gemm_kernel<<<dim3(NN/GT_M, 24), 256>>>(s,
        wq, bq, wk, bk, wv, bv, wqp, bqp, wkp, bkp, wvp, bvp);
    rotate_points_kernel<<<NN, 192>>>(rot, trans);
    attn_kernel<<<NN, 384, SMEM_BYTES>>>(z, trans, rot, mask, wb, bb);
    out_gemm_kernel<<<dim3(NN/GT_M, COUT/GT_N), 256>>>(wo, bo, out);
}

// round 6
// speedup vs baseline: 2.2509x; 1.5394x over previous
#include <cuda_runtime.h>
#include <math.h>

// Problem constants
#define NN    512
#define CS    384
#define CZ    128
#define HH    12
#define CH    16
#define PQN   4
#define PVN   8
#define DPROJ 1152
#define FH    (CH + PVN*3 + PVN + CZ)  // 176
#define FEAT  (HH*FH)                  // 2112
#define COUT  384

// segment bases inside g_proj row
#define OFF_PQ_Q   0
#define OFF_PQ_K   192
#define OFF_PQ_V   384
#define OFF_PQ_QP  576
#define OFF_PQ_KP  720
#define OFF_PQ_VP  864

// ---------------- scratch ----------------
__device__ __align__(16) float g_proj[NN*DPROJ];
__device__ __align__(16) float g_qpg [NN*HH*PQN*3];
__device__ __align__(16) float g_kpg [NN*HH*PQN*3];
__device__ __align__(16) float g_vpg [NN*HH*PVN*3];
__device__ __align__(16) float g_feat[NN*FEAT];
#define SPLITS 4
__device__ __align__(16) float g_opart[SPLITS][NN][COUT];

// =================== fused projection SGEMM ===========================
// tile 64 x 48, K-chunk 16, 192 threads, 4x4 micro-tile (float4 LDS)
#define PT_M 64
#define PT_N 48
#define PT_K 16
__global__ void proj_gemm_kernel(const float* __restrict__ s,
    const float* __restrict__ wq,  const float* __restrict__ bq,
    const float* __restrict__ wk,  const float* __restrict__ bk,
    const float* __restrict__ wv,  const float* __restrict__ bv,
    const float* __restrict__ wqp, const float* __restrict__ bqp,
    const float* __restrict__ wkp, const float* __restrict__ bkp,
    const float* __restrict__ wvp, const float* __restrict__ bvp) {
    int bt = blockIdx.y;
    const float *W, *B; int Dout, base, t;
    if      (bt < 4)  { W=wq;  B=bq;  Dout=192; base=OFF_PQ_Q;  t=bt; }
    else if (bt < 8)  { W=wk;  B=bk;  Dout=192; base=OFF_PQ_K;  t=bt-4; }
    else if (bt < 12) { W=wv;  B=bv;  Dout=192; base=OFF_PQ_V;  t=bt-8; }
    else if (bt < 15) { W=wqp; B=bqp; Dout=144; base=OFF_PQ_QP; t=bt-12; }
    else if (bt < 18) { W=wkp; B=bkp; Dout=144; base=OFF_PQ_KP; t=bt-15; }
    else              { W=wvp; B=bvp; Dout=288; base=OFF_PQ_VP; t=bt-18; }
    int col0 = t*PT_N;
    int n0   = blockIdx.x*PT_M;

    __shared__ float sA[PT_K][PT_M];
    __shared__ float sB[PT_K][PT_N];
    int tid = threadIdx.x;           // 192
    int tx = tid % 12, ty = tid / 12;   // cols, rows
    float4 acc[4] = {};

    for (int k0 = 0; k0 < CS; k0 += PT_K) {
        // A: 64 rows x 16 k, transposed stores (coalesced float4 reads along k)
        for (int i = tid; i < PT_M*PT_K/4; i += 192) {
            int m = i >> 2, k4 = (i & 3) * 4;
            float4 v = *(const float4*)(s + (size_t)(n0+m)*CS + k0 + k4);
            sA[k4+0][m]=v.x; sA[k4+1][m]=v.y; sA[k4+2][m]=v.z; sA[k4+3][m]=v.w;
        }
        // B: 16 k x 48 cols
        for (int i = tid; i < PT_K*PT_N/4; i += 192) {
            int k = i / 12, c4 = (i % 12) * 4;
            *(float4*)&sB[k][c4] = *(const float4*)(W + (size_t)(k0+k)*Dout + col0 + c4);
        }
        __syncthreads();
        #pragma unroll
        for (int kk = 0; kk < PT_K; kk++) {
            float4 b = *(float4*)&sB[kk][tx*4];
            float4 a = *(float4*)&sA[kk][ty*4];
            acc[0].x += a.x*b.x; acc[0].y += a.x*b.y; acc[0].z += a.x*b.z; acc[0].w += a.x*b.w;
            acc[1].x += a.y*b.x; acc[1].y += a.y*b.y; acc[1].z += a.y*b.z; acc[1].w += a.y*b.w;
            acc[2].x += a.z*b.x; acc[2].y += a.z*b.y; acc[2].z += a.z*b.z; acc[2].w += a.z*b.w;
            acc[3].x += a.w*b.x; acc[3].y += a.w*b.y; acc[3].z += a.w*b.z; acc[3].w += a.w*b.w;
        }
        __syncthreads();
    }
    float4 bias4 = *(const float4*)(B + col0 + tx*4);
    #pragma unroll
    for (int r = 0; r < 4; r++) {
        float4 o = acc[r];
        o.x += bias4.x; o.y += bias4.y; o.z += bias4.z; o.w += bias4.w;
        *(float4*)(g_proj + (size_t)(n0+ty*4+r)*DPROJ + base + col0 + tx*4) = o;
    }
}

// =================== rotation epilogue for point projections ==========
__global__ void rotate_points_kernel(const float* __restrict__ rot,
                                     const float* __restrict__ trans) {
    int n = blockIdx.x, t = threadIdx.x;
    __shared__ float R[9], T[3];
    if (t < 9) R[t] = rot[n*9 + t];
    if (t < 3) T[t] = trans[n*3 + t];
    __syncthreads();
    int src_off, hp; float* dst;
    if      (t < 48)  { hp = t;      src_off = OFF_PQ_QP; dst = g_qpg + n*144; }
    else if (t < 96)  { hp = t-48;   src_off = OFF_PQ_KP; dst = g_kpg + n*144; }
    else              { hp = t-96;   src_off = OFF_PQ_VP; dst = g_vpg + n*288; }
    const float* l = g_proj + (size_t)n*DPROJ + src_off + hp*3;
    float l0=l[0], l1=l[1], l2=l[2];
    dst[hp*3+0] = R[0]*l0 + R[1]*l1 + R[2]*l2 + T[0];
    dst[hp*3+1] = R[3]*l0 + R[4]*l1 + R[5]*l2 + T[1];
    dst[hp*3+2] = R[6]*l0 + R[7]*l1 + R[8]*l2 + T[2];
}

// =================== fused attention per query row ====================
#define TM1 32
#define TM2 16
#define WB_STRIDE 132

#define OFF_Q     0
#define OFF_QPG   (OFF_Q + 192)
#define OFF_WB    (OFF_QPG + 144)
#define OFF_BB    (OFF_WB + HH*WB_STRIDE)
#define OFF_LOG   (OFF_BB + 12)
#define OFF_ACC   (OFF_LOG + NN*HH)
#define OFF_DN    (OFF_ACC + HH*168)
#define OFF_R     (OFF_DN + 12)
#define OFF_T     (OFF_R + 9)
#define OFF_TILE  (OFF_T + 3)
#define TILE_FLOATS 14848
#define SMEM_FLOATS (OFF_TILE + TILE_FLOATS)
#define SMEM_BYTES  (SMEM_FLOATS * 4)

__global__ void attn_kernel(const float* __restrict__ z,
                            const float* __restrict__ trans,
                            const float* __restrict__ rot,
                            const int*   __restrict__ mask,
                            const float* __restrict__ wb,
                            const float* __restrict__ bb) {
    extern __shared__ float sm[];
    float* q_s    = sm + OFF_Q;
    float* qpg_s  = sm + OFF_QPG;
    float* wb_s   = sm + OFF_WB;
    float* bb_s   = sm + OFF_BB;
    float* logits = sm + OFF_LOG;
    float* acc    = sm + OFF_ACC;
    float* dn     = sm + OFF_DN;
    float* R      = sm + OFF_R;
    float* T      = sm + OFF_T;
    float* tile   = sm + OFF_TILE;

    int n = blockIdx.x, tid = threadIdx.x;

    for (int i = tid; i < 192; i += 384) q_s[i]   = g_proj[(size_t)n*DPROJ + i];
    for (int i = tid; i < 144; i += 384) qpg_s[i] = g_qpg[n*144 + i];
    for (int i = tid; i < CZ*HH; i += 384) {
        int c = i / HH, h = i % HH;
        wb_s[h*WB_STRIDE + c] = wb[i];
    }
    if (tid < 12) bb_s[tid] = bb[tid];
    if (tid < 9)  R[tid] = rot[n*9 + tid];
    if (tid < 3)  T[tid] = trans[n*3 + tid];
    int mask_n = mask[n];
    __syncthreads();

    // ---------------- pass 1: logits ------------------------------------
    const int ml = tid / HH;
    const int h1 = tid % HH;
    for (int m0 = 0; m0 < NN; m0 += TM1) {
        float4* kt  = (float4*)(tile);
        float4* kpt = (float4*)(tile + TM1*192);
        float4* zt  = (float4*)(tile + TM1*(192+144));
        for (int i = tid; i < TM1*48; i += 384) {
            int r = i / 48, c = i % 48;
            kt[i] = ((const float4*)(g_proj + (size_t)(m0+r)*DPROJ + OFF_PQ_K))[c];
        }
        {
            const float4* gkp = (const float4*)(g_kpg + m0*144);
            for (int i = tid; i < TM1*36; i += 384) kpt[i] = gkp[i];
            const float4* gz = (const float4*)(z + ((size_t)n*NN + m0)*CZ);
            for (int i = tid; i < TM1*32; i += 384) zt[i] = gz[i];
        }
        __syncthreads();
        {
            const float4* kr4  = (const float4*)(tile + ml*192 + h1*CH);
            const float4* qr4  = (const float4*)(q_s + h1*CH);
            float sc = 0.f;
            #pragma unroll
            for (int c = 0; c < 4; c++) {
                float4 a = qr4[c], b = kr4[c];
                sc += a.x*b.x + a.y*b.y + a.z*b.z + a.w*b.w;
            }
            float logit = sc * 0.25f;
            const float4* kp4 = (const float4*)(tile + TM1*192 + ml*144 + h1*12);
            const float4* qp4 = (const float4*)(qpg_s + h1*12);
            float ss = 0.f;
            #pragma unroll
            for (int c = 0; c < 3; c++) {
                float4 a = qp4[c], b = kp4[c];
                float dx=a.x-b.x, dy=a.y-b.y, dz=a.z-b.z, dw=a.w-b.w;
                ss += dx*dx + dy*dy + dz*dz + dw*dw;
            }
            logit -= 0.5f * ss;
            const float4* zr4 = (const float4*)(tile + TM1*(192+144) + ml*CZ);
            const float4* wr4 = (const float4*)(wb_s + h1*WB_STRIDE);
            float bz = bb_s[h1];
            #pragma unroll
            for (int c4 = 0; c4 < CZ/4; c4++) {
                float4 zv = zr4[c4], wv = wr4[c4];
                bz += zv.x*wv.x + zv.y*wv.y + zv.z*wv.z + zv.w*wv.w;
            }
            logit += bz;
            int m = m0 + ml;
            if (mask_n == 0 || mask[m] == 0) logit = -1e30f;
            logits[m*HH + h1] = logit;
        }
        __syncthreads();
    }

    // ---------------- softmax: one warp per head --------------------------
    {
        int w = tid >> 5, lane = tid & 31;
        float mx = -1e30f;
        for (int m = lane; m < NN; m += 32) mx = fmaxf(mx, logits[m*HH + w]);
        #pragma unroll
        for (int o = 16; o; o >>= 1) mx = fmaxf(mx, __shfl_xor_sync(0xffffffffu, mx, o));
        float s = 0.f;
        for (int m = lane; m < NN; m += 32) {
            float e = __expf(logits[m*HH + w] - mx);
            logits[m*HH + w] = e;
            s += e;
        }
        #pragma unroll
        for (int o = 16; o; o >>= 1) s += __shfl_xor_sync(0xffffffffu, s, o);
        if (lane == 0) dn[w] = s;
    }
    __syncthreads();

    // ---------------- pass 2: weighted sums --------------------------------
    int s0 = tid, s1 = tid + 384;
    bool has1 = (s1 < HH*42);
    int h0 = s0/42, g0 = s0%42, j0 = g0*4;
    int h1b = has1 ? s1/42 : 0, g1 = has1 ? s1%42 : 0, j1 = g1*4;

    const float* x0; int st0;
    if (j0 < 16)      { x0 = tile + h0*CH + j0;                    st0 = 192; }
    else if (j0 < 40) { x0 = tile + TM2*192 + h0*24 + (j0-16);     st0 = 288; }
    else              { x0 = tile + TM2*(192+288) + (j0-40);       st0 = 128; }
    const float* x1 = tile; int st1 = 192;
    if (has1) {
        if (j1 < 16)      { x1 = tile + h1b*CH + j1;                  st1 = 192; }
        else if (j1 < 40) { x1 = tile + TM2*192 + h1b*24 + (j1-16);   st1 = 288; }
        else              { x1 = tile + TM2*(192+288) + (j1-40);      st1 = 128; }
    }
    float4 a0 = {0,0,0,0}, a1 = {0,0,0,0};

    for (int m0 = 0; m0 < NN; m0 += TM2) {
        float4* vt  = (float4*)(tile);
        float4* vpt = (float4*)(tile + TM2*192);
        float4* zt  = (float4*)(tile + TM2*(192+288));
        for (int i = tid; i < TM2*48; i += 384) {
            int r = i / 48, c = i % 48;
            vt[i] = ((const float4*)(g_proj + (size_t)(m0+r)*DPROJ + OFF_PQ_V))[c];
        }
        {
            const float4* gvp = (const float4*)(g_vpg + m0*288);
            for (int i = tid; i < TM2*72; i += 384) vpt[i] = gvp[i];
            const float4* gz = (const float4*)(z + ((size_t)n*NN + m0)*CZ);
            for (int i = tid; i < TM2*32; i += 384) zt[i] = gz[i];
        }
        __syncthreads();
        const float* w0r = logits + m0*HH + h0;
        const float* w1r = logits + m0*HH + h1b;
        #pragma unroll 8
        for (int mm = 0; mm < TM2; mm++) {
            float w0v = w0r[mm*HH];
            float4 xv = *(const float4*)(x0 + mm*st0);
            a0.x += w0v*xv.x; a0.y += w0v*xv.y; a0.z += w0v*xv.z; a0.w += w0v*xv.w;
            if (has1) {
                float w1v = w1r[mm*HH];
                float4 yv = *(const float4*)(x1 + mm*st1);
                a1.x += w1v*yv.x; a1.y += w1v*yv.y; a1.z += w1v*yv.z; a1.w += w1v*yv.w;
            }
        }
        __syncthreads();
    }
    *(float4*)(acc + h0*168 + j0) = a0;
    if (has1) *(float4*)(acc + h1b*168 + j1) = a1;
    __syncthreads();

    // ---------------- finalize -------------------------------------------
    for (int s_ = tid; s_ < HH*168; s_ += 384) {
        int h = s_/168, j = s_%168;
        float val = acc[s_] / dn[h];
        if (j < 16)       g_feat[(size_t)n*FEAT + h*FH + j] = val;
        else if (j >= 40) g_feat[(size_t)n*FEAT + h*FH + 48 + (j-40)] = val;
    }
    if (tid < HH*PVN) {
        int h = tid / PVN, p = tid % PVN;
        float inv = 1.f / dn[h];
        float x0_ = acc[h*168 + 16 + p*3 + 0]*inv - T[0];
        float x1_ = acc[h*168 + 16 + p*3 + 1]*inv - T[1];
        float x2_ = acc[h*168 + 16 + p*3 + 2]*inv - T[2];
        float l0 = R[0]*x0_ + R[3]*x1_ + R[6]*x2_;
        float l1 = R[1]*x0_ + R[4]*x1_ + R[7]*x2_;
        float l2 = R[2]*x0_ + R[5]*x1_ + R[8]*x2_;
        g_feat[(size_t)n*FEAT + h*FH + 16 + p*3 + 0] = l0;
        g_feat[(size_t)n*FEAT + h*FH + 16 + p*3 + 1] = l1;
        g_feat[(size_t)n*FEAT + h*FH + 16 + p*3 + 2] = l2;
        g_feat[(size_t)n*FEAT + h*FH + 40 + p] = sqrtf(l0*l0 + l1*l1 + l2*l2);
    }
}

// =================== output projection: split-K SGEMM ==================
// 512x384x2112, tile 64x64, K split in 4 slabs of 528, 256 threads, 4x4 micro
#define OT_M 64
#define OT_N 64
#define OT_K 16
#define KSPLIT (FEAT/SPLITS)   // 528
__global__ void out_gemm_kernel(const float* __restrict__ wo) {
    int n0   = blockIdx.x*OT_M;
    int col0 = blockIdx.y*OT_N;
    int sp   = blockIdx.z;
    __shared__ float sA[OT_K][OT_M];
    __shared__ float sB[OT_K][OT_N];
    int tid = threadIdx.x;          // 256
    int tx = tid & 15, ty = tid >> 4;
    float4 acc[4] = {};
    int kbeg = sp*KSPLIT, kend = kbeg + KSPLIT;
    for (int k0 = kbeg; k0 < kend; k0 += OT_K) {
        for (int i = tid; i < OT_M*OT_K/4; i += 256) {
            int m = i >> 2, k4 = (i & 3) * 4;
            float4 v = *(const float4*)(g_feat + (size_t)(n0+m)*FEAT + k0 + k4);
            sA[k4+0][m]=v.x; sA[k4+1][m]=v.y; sA[k4+2][m]=v.z; sA[k4+3][m]=v.w;
        }
        for (int i = tid; i < OT_K*OT_N/4; i += 256) {
            int k = i >> 4, c4 = (i & 15) * 4;
            *(float4*)&sB[k][c4] = *(const float4*)(wo + (size_t)(k0+k)*COUT + col0 + c4);
        }
        __syncthreads();
        #pragma unroll
        for (int kk = 0; kk < OT_K; kk++) {
            float4 b = *(float4*)&sB[kk][tx*4];
            float4 a = *(float4*)&sA[kk][ty*4];
            acc[0].x += a.x*b.x; acc[0].y += a.x*b.y; acc[0].z += a.x*b.z; acc[0].w += a.x*b.w;
            acc[1].x += a.y*b.x; acc[1].y += a.y*b.y; acc[1].z += a.y*b.z; acc[1].w += a.y*b.w;
            acc[2].x += a.z*b.x; acc[2].y += a.z*b.y; acc[2].z += a.z*b.z; acc[2].w += a.z*b.w;
            acc[3].x += a.w*b.x; acc[3].y += a.w*b.y; acc[3].z += a.w*b.z; acc[3].w += a.w*b.w;
        }
        __syncthreads();
    }
    #pragma unroll
    for (int r = 0; r < 4; r++)
        *(float4*)&g_opart[sp][n0+ty*4+r][col0+tx*4] = acc[r];
}

__global__ void out_reduce_kernel(const float* __restrict__ bo,
                                  float* __restrict__ out) {
    int n = blockIdx.x, o = threadIdx.x;   // 384 threads
    float a = bo[o];
    #pragma unroll
    for (int sp = 0; sp < SPLITS; sp++) a += g_opart[sp][n][o];
    out[(size_t)n*COUT + o] = a;
}

// ---------------- launch ---------------------------------------------------
extern "C" void kernel_launch(void* const* d_in, const int* in_sizes, int n_in,
                              void* d_out, int out_size) {
    const float* s     = (const float*)d_in[0];
    const float* z     = (const float*)d_in[1];
    const float* trans = (const float*)d_in[2];
    const float* rot   = (const float*)d_in[3];
    const int*   mask  = (const int*)  d_in[4];
    const float* wq    = (const float*)d_in[5];
    const float* bq    = (const float*)d_in[6];
    const float* wk    = (const float*)d_in[7];
    const float* bk    = (const float*)d_in[8];
    const float* wv    = (const float*)d_in[9];
    const float* bv    = (const float*)d_in[10];
    const float* wqp   = (const float*)d_in[11];
    const float* bqp   = (const float*)d_in[12];
    const float* wkp   = (const float*)d_in[13];
    const float* bkp   = (const float*)d_in[14];
    const float* wvp   = (const float*)d_in[15];
    const float* bvp   = (const float*)d_in[16];
    const float* wb    = (const float*)d_in[17];
    const float* bb    = (const float*)d_in[18];
    const float* wo    = (const float*)d_in[19];
    const float* bo    = (const float*)d_in[20];
    float* out = (float*)d_out;

    cudaFuncSetAttribute(attn_kernel,
                         cudaFuncAttributeMaxDynamicSharedMemorySize, SMEM_BYTES);

    proj_gemm_kernel<<<dim3(NN/PT_M, 24), 192>>>(s,
        wq, bq, wk, bk, wv, bv, wqp, bqp, wkp, bkp, wvp, bvp);
    rotate_points_kernel<<<NN, 192>>>(rot, trans);
    attn_kernel<<<NN, 384, SMEM_BYTES>>>(z, trans, rot, mask, wb, bb);
    out_gemm_kernel<<<dim3(NN/OT_M, COUT/OT_N, SPLITS), 256>>>(wo);
    out_reduce_kernel<<<NN, COUT>>>(bo, out);
}

// round 8
// speedup vs baseline: 2.7287x; 1.2123x over previous
#include <cuda_runtime.h>
#include <math.h>

// Problem constants
#define NN    512
#define CS    384
#define CZ    128
#define HH    12
#define CH    16
#define PQN   4
#define PVN   8
#define DPROJ 1152
#define FH    (CH + PVN*3 + PVN + CZ)  // 176
#define FEAT  (HH*FH)                  // 2112
#define COUT  384

// segment bases inside g_proj row
#define OFF_PQ_Q   0
#define OFF_PQ_K   192
#define OFF_PQ_V   384
#define OFF_PQ_QP  576
#define OFF_PQ_KP  720
#define OFF_PQ_VP  864

// ---------------- scratch ----------------
__device__ __align__(16) float g_proj[NN*DPROJ];
__device__ __align__(16) float g_qpg [NN*HH*PQN*3];
__device__ __align__(16) float g_kpg [NN*HH*PQN*3];
__device__ __align__(16) float g_vpg [NN*HH*PVN*3];
__device__ __align__(16) float g_feat[NN*FEAT];
__device__ __align__(16) float g_zb  [(size_t)NN*NN*HH];   // 12.6 MB
#define SPLITS 4
__device__ __align__(16) float g_opart[SPLITS][NN][COUT];

// =================== fused projection SGEMM ===========================
#define PT_M 64
#define PT_N 48
#define PT_K 16
__global__ void proj_gemm_kernel(const float* __restrict__ s,
    const float* __restrict__ wq,  const float* __restrict__ bq,
    const float* __restrict__ wk,  const float* __restrict__ bk,
    const float* __restrict__ wv,  const float* __restrict__ bv,
    const float* __restrict__ wqp, const float* __restrict__ bqp,
    const float* __restrict__ wkp, const float* __restrict__ bkp,
    const float* __restrict__ wvp, const float* __restrict__ bvp) {
    int bt = blockIdx.y;
    const float *W, *B; int Dout, base, t;
    if      (bt < 4)  { W=wq;  B=bq;  Dout=192; base=OFF_PQ_Q;  t=bt; }
    else if (bt < 8)  { W=wk;  B=bk;  Dout=192; base=OFF_PQ_K;  t=bt-4; }
    else if (bt < 12) { W=wv;  B=bv;  Dout=192; base=OFF_PQ_V;  t=bt-8; }
    else if (bt < 15) { W=wqp; B=bqp; Dout=144; base=OFF_PQ_QP; t=bt-12; }
    else if (bt < 18) { W=wkp; B=bkp; Dout=144; base=OFF_PQ_KP; t=bt-15; }
    else              { W=wvp; B=bvp; Dout=288; base=OFF_PQ_VP; t=bt-18; }
    int col0 = t*PT_N;
    int n0   = blockIdx.x*PT_M;

    __shared__ float sA[PT_K][PT_M];
    __shared__ float sB[PT_K][PT_N];
    int tid = threadIdx.x;           // 192
    int tx = tid % 12, ty = tid / 12;
    float4 acc[4] = {};

    for (int k0 = 0; k0 < CS; k0 += PT_K) {
        for (int i = tid; i < PT_M*PT_K/4; i += 192) {
            int m = i >> 2, k4 = (i & 3) * 4;
            float4 v = *(const float4*)(s + (size_t)(n0+m)*CS + k0 + k4);
            sA[k4+0][m]=v.x; sA[k4+1][m]=v.y; sA[k4+2][m]=v.z; sA[k4+3][m]=v.w;
        }
        for (int i = tid; i < PT_K*PT_N/4; i += 192) {
            int k = i / 12, c4 = (i % 12) * 4;
            *(float4*)&sB[k][c4] = *(const float4*)(W + (size_t)(k0+k)*Dout + col0 + c4);
        }
        __syncthreads();
        #pragma unroll
        for (int kk = 0; kk < PT_K; kk++) {
            float4 b = *(float4*)&sB[kk][tx*4];
            float4 a = *(float4*)&sA[kk][ty*4];
            acc[0].x += a.x*b.x; acc[0].y += a.x*b.y; acc[0].z += a.x*b.z; acc[0].w += a.x*b.w;
            acc[1].x += a.y*b.x; acc[1].y += a.y*b.y; acc[1].z += a.y*b.z; acc[1].w += a.y*b.w;
            acc[2].x += a.z*b.x; acc[2].y += a.z*b.y; acc[2].z += a.z*b.z; acc[2].w += a.z*b.w;
            acc[3].x += a.w*b.x; acc[3].y += a.w*b.y; acc[3].z += a.w*b.z; acc[3].w += a.w*b.w;
        }
        __syncthreads();
    }
    float4 bias4 = *(const float4*)(B + col0 + tx*4);
    #pragma unroll
    for (int r = 0; r < 4; r++) {
        float4 o = acc[r];
        o.x += bias4.x; o.y += bias4.y; o.z += bias4.z; o.w += bias4.w;
        *(float4*)(g_proj + (size_t)(n0+ty*4+r)*DPROJ + base + col0 + tx*4) = o;
    }
}

// =================== rotation epilogue for point projections ==========
__global__ void rotate_points_kernel(const float* __restrict__ rot,
                                     const float* __restrict__ trans) {
    int n = blockIdx.x, t = threadIdx.x;
    __shared__ float R[9], T[3];
    if (t < 9) R[t] = rot[n*9 + t];
    if (t < 3) T[t] = trans[n*3 + t];
    __syncthreads();
    int src_off, hp; float* dst;
    if      (t < 48)  { hp = t;      src_off = OFF_PQ_QP; dst = g_qpg + n*144; }
    else if (t < 96)  { hp = t-48;   src_off = OFF_PQ_KP; dst = g_kpg + n*144; }
    else              { hp = t-96;   src_off = OFF_PQ_VP; dst = g_vpg + n*288; }
    const float* l = g_proj + (size_t)n*DPROJ + src_off + hp*3;
    float l0=l[0], l1=l[1], l2=l[2];
    dst[hp*3+0] = R[0]*l0 + R[1]*l1 + R[2]*l2 + T[0];
    dst[hp*3+1] = R[3]*l0 + R[4]*l1 + R[5]*l2 + T[1];
    dst[hp*3+2] = R[6]*l0 + R[7]*l1 + R[8]*l2 + T[2];
}

// =================== z-bias GEMM: zb[row, h] = z[row,:]@wb[:,h]+bb ====
// rows = NN*NN = 262144, 4 rows per thread, 128 threads, 512 blocks
#define ZB_THREADS 128
#define ZB_ROWS    4
__global__ void zb_gemm_kernel(const float* __restrict__ z,
                               const float* __restrict__ wb,
                               const float* __restrict__ bb) {
    __shared__ float wb_s[CZ*HH];
    __shared__ float bb_s[HH];
    int tid = threadIdx.x;
    for (int i = tid; i < CZ*HH; i += ZB_THREADS) wb_s[i] = wb[i];
    if (tid < HH) bb_s[tid] = bb[tid];
    __syncthreads();

    size_t row0 = ((size_t)blockIdx.x*ZB_THREADS + tid) * ZB_ROWS;
    float acc[ZB_ROWS][HH];
    #pragma unroll
    for (int r = 0; r < ZB_ROWS; r++)
        #pragma unroll
        for (int h = 0; h < HH; h++) acc[r][h] = bb_s[h];

    const float* zp = z + row0*CZ;
    #pragma unroll 4
    for (int k4 = 0; k4 < CZ/4; k4++) {
        float4 zv[ZB_ROWS];
        #pragma unroll
        for (int r = 0; r < ZB_ROWS; r++)
            zv[r] = *(const float4*)(zp + (size_t)r*CZ + k4*4);
        #pragma unroll
        for (int kk = 0; kk < 4; kk++) {
            const float* wrow = wb_s + (k4*4+kk)*HH;
            #pragma unroll
            for (int h = 0; h < HH; h++) {
                float w = wrow[h];
                acc[0][h] += ((const float*)&zv[0])[kk] * w;
                acc[1][h] += ((const float*)&zv[1])[kk] * w;
                acc[2][h] += ((const float*)&zv[2])[kk] * w;
                acc[3][h] += ((const float*)&zv[3])[kk] * w;
            }
        }
    }
    // 48 contiguous floats starting at row0*12
    float* op = g_zb + row0*HH;
    #pragma unroll
    for (int r = 0; r < ZB_ROWS; r++)
        #pragma unroll
        for (int h = 0; h < HH; h++) op[r*HH + h] = acc[r][h];
}

// =================== fused attention per query row ====================
#define TM2 16

#define OFF_Q     0                      // 192
#define OFF_QPG   (OFF_Q + 192)          // 144
#define OFF_LOG   (OFF_QPG + 144)        // 6144
#define OFF_ACC   (OFF_LOG + NN*HH)      // 2016
#define OFF_DN    (OFF_ACC + HH*168)     // 12
#define OFF_R     (OFF_DN + 12)          // 9
#define OFF_T     (OFF_R + 9)            // 3
#define OFF_TILE  (OFF_T + 3)            // 16*608 = 9728
#define TILE_FLOATS (TM2*608)
#define SMEM_FLOATS (OFF_TILE + TILE_FLOATS)
#define SMEM_BYTES  (SMEM_FLOATS * 4)

__global__ void attn_kernel(const float* __restrict__ z,
                            const float* __restrict__ trans,
                            const float* __restrict__ rot,
                            const int*   __restrict__ mask,
                            const float* __restrict__ dummy_wb,
                            const float* __restrict__ dummy_bb) {
    extern __shared__ float sm[];
    float* q_s    = sm + OFF_Q;
    float* qpg_s  = sm + OFF_QPG;
    float* logits = sm + OFF_LOG;
    float* acc    = sm + OFF_ACC;
    float* dn     = sm + OFF_DN;
    float* R      = sm + OFF_R;
    float* T      = sm + OFF_T;
    float* tile   = sm + OFF_TILE;

    int n = blockIdx.x, tid = threadIdx.x;

    for (int i = tid; i < 192; i += 384) q_s[i]   = g_proj[(size_t)n*DPROJ + i];
    for (int i = tid; i < 144; i += 384) qpg_s[i] = g_qpg[n*144 + i];
    if (tid < 9)  R[tid] = rot[n*9 + tid];
    if (tid < 3)  T[tid] = trans[n*3 + tid];
    int mask_n = mask[n];
    __syncthreads();

    // ---------------- pass 1: streaming logits (no staging, no syncs) ----
    {
        const int ml0 = tid / HH;    // 0..31
        const int h   = tid % HH;
        // preload q and qpg for this head into registers
        float4 qv[4], qp[3];
        #pragma unroll
        for (int c = 0; c < 4; c++) qv[c] = ((const float4*)(q_s + h*CH))[c];
        #pragma unroll
        for (int c = 0; c < 3; c++) qp[c] = ((const float4*)(qpg_s + h*12))[c];

        const float* zb_n = g_zb + (size_t)n*NN*HH;
        for (int m = ml0; m < NN; m += 32) {
            const float4* kr = (const float4*)(g_proj + (size_t)m*DPROJ + OFF_PQ_K + h*CH);
            float sc = 0.f;
            #pragma unroll
            for (int c = 0; c < 4; c++) {
                float4 b = __ldg(&kr[c]);
                sc += qv[c].x*b.x + qv[c].y*b.y + qv[c].z*b.z + qv[c].w*b.w;
            }
            float logit = sc * 0.25f;
            const float4* kp = (const float4*)(g_kpg + m*144 + h*12);
            float ss = 0.f;
            #pragma unroll
            for (int c = 0; c < 3; c++) {
                float4 b = __ldg(&kp[c]);
                float dx=qp[c].x-b.x, dy=qp[c].y-b.y, dz=qp[c].z-b.z, dw=qp[c].w-b.w;
                ss += dx*dx + dy*dy + dz*dz + dw*dw;
            }
            logit -= 0.5f * ss;
            logit += __ldg(zb_n + m*HH + h);
            if (mask_n == 0 || __ldg(mask + m) == 0) logit = -1e30f;
            logits[m*HH + h] = logit;
        }
    }
    __syncthreads();

    // ---------------- softmax: one warp per head --------------------------
    {
        int w = tid >> 5, lane = tid & 31;
        float mx = -1e30f;
        for (int m = lane; m < NN; m += 32) mx = fmaxf(mx, logits[m*HH + w]);
        #pragma unroll
        for (int o = 16; o; o >>= 1) mx = fmaxf(mx, __shfl_xor_sync(0xffffffffu, mx, o));
        float s = 0.f;
        for (int m = lane; m < NN; m += 32) {
            float e = __expf(logits[m*HH + w] - mx);
            logits[m*HH + w] = e;
            s += e;
        }
        #pragma unroll
        for (int o = 16; o; o >>= 1) s += __shfl_xor_sync(0xffffffffu, s, o);
        if (lane == 0) dn[w] = s;
    }
    __syncthreads();

    // ---------------- pass 2: weighted sums --------------------------------
    int s0 = tid, s1 = tid + 384;
    bool has1 = (s1 < HH*42);
    int h0 = s0/42, g0 = s0%42, j0 = g0*4;
    int h1b = has1 ? s1/42 : 0, g1 = has1 ? s1%42 : 0, j1 = g1*4;

    const float* x0; int st0;
    if (j0 < 16)      { x0 = tile + h0*CH + j0;                    st0 = 192; }
    else if (j0 < 40) { x0 = tile + TM2*192 + h0*24 + (j0-16);     st0 = 288; }
    else              { x0 = tile + TM2*(192+288) + (j0-40);       st0 = 128; }
    const float* x1 = tile; int st1 = 192;
    if (has1) {
        if (j1 < 16)      { x1 = tile + h1b*CH + j1;                  st1 = 192; }
        else if (j1 < 40) { x1 = tile + TM2*192 + h1b*24 + (j1-16);   st1 = 288; }
        else              { x1 = tile + TM2*(192+288) + (j1-40);      st1 = 128; }
    }
    float4 a0 = {0,0,0,0}, a1 = {0,0,0,0};

    for (int m0 = 0; m0 < NN; m0 += TM2) {
        float4* vt  = (float4*)(tile);
        float4* vpt = (float4*)(tile + TM2*192);
        float4* zt  = (float4*)(tile + TM2*(192+288));
        for (int i = tid; i < TM2*48; i += 384) {
            int r = i / 48, c = i % 48;
            vt[i] = ((const float4*)(g_proj + (size_t)(m0+r)*DPROJ + OFF_PQ_V))[c];
        }
        {
            const float4* gvp = (const float4*)(g_vpg + m0*288);
            for (int i = tid; i < TM2*72; i += 384) vpt[i] = gvp[i];
            const float4* gz = (const float4*)(z + ((size_t)n*NN + m0)*CZ);
            for (int i = tid; i < TM2*32; i += 384) zt[i] = gz[i];
        }
        __syncthreads();
        const float* w0r = logits + m0*HH + h0;
        const float* w1r = logits + m0*HH + h1b;
        #pragma unroll 8
        for (int mm = 0; mm < TM2; mm++) {
            float w0v = w0r[mm*HH];
            float4 xv = *(const float4*)(x0 + mm*st0);
            a0.x += w0v*xv.x; a0.y += w0v*xv.y; a0.z += w0v*xv.z; a0.w += w0v*xv.w;
            if (has1) {
                float w1v = w1r[mm*HH];
                float4 yv = *(const float4*)(x1 + mm*st1);
                a1.x += w1v*yv.x; a1.y += w1v*yv.y; a1.z += w1v*yv.z; a1.w += w1v*yv.w;
            }
        }
        __syncthreads();
    }
    *(float4*)(acc + h0*168 + j0) = a0;
    if (has1) *(float4*)(acc + h1b*168 + j1) = a1;
    __syncthreads();

    // ---------------- finalize -------------------------------------------
    for (int s_ = tid; s_ < HH*168; s_ += 384) {
        int h = s_/168, j = s_%168;
        float val = acc[s_] / dn[h];
        if (j < 16)       g_feat[(size_t)n*FEAT + h*FH + j] = val;
        else if (j >= 40) g_feat[(size_t)n*FEAT + h*FH + 48 + (j-40)] = val;
    }
    if (tid < HH*PVN) {
        int h = tid / PVN, p = tid % PVN;
        float inv = 1.f / dn[h];
        float x0_ = acc[h*168 + 16 + p*3 + 0]*inv - T[0];
        float x1_ = acc[h*168 + 16 + p*3 + 1]*inv - T[1];
        float x2_ = acc[h*168 + 16 + p*3 + 2]*inv - T[2];
        float l0 = R[0]*x0_ + R[3]*x1_ + R[6]*x2_;
        float l1 = R[1]*x0_ + R[4]*x1_ + R[7]*x2_;
        float l2 = R[2]*x0_ + R[5]*x1_ + R[8]*x2_;
        g_feat[(size_t)n*FEAT + h*FH + 16 + p*3 + 0] = l0;
        g_feat[(size_t)n*FEAT + h*FH + 16 + p*3 + 1] = l1;
        g_feat[(size_t)n*FEAT + h*FH + 16 + p*3 + 2] = l2;
        g_feat[(size_t)n*FEAT + h*FH + 40 + p] = sqrtf(l0*l0 + l1*l1 + l2*l2);
    }
}

// =================== output projection: split-K SGEMM ==================
#define OT_M 64
#define OT_N 64
#define OT_K 16
#define KSPLIT (FEAT/SPLITS)   // 528
__global__ void out_gemm_kernel(const float* __restrict__ wo) {
    int n0   = blockIdx.x*OT_M;
    int col0 = blockIdx.y*OT_N;
    int sp   = blockIdx.z;
    __shared__ float sA[OT_K][OT_M];
    __shared__ float sB[OT_K][OT_N];
    int tid = threadIdx.x;
    int tx = tid & 15, ty = tid >> 4;
    float4 acc[4] = {};
    int kbeg = sp*KSPLIT, kend = kbeg + KSPLIT;
    for (int k0 = kbeg; k0 < kend; k0 += OT_K) {
        for (int i = tid; i < OT_M*OT_K/4; i += 256) {
            int m = i >> 2, k4 = (i & 3) * 4;
            float4 v = *(const float4*)(g_feat + (size_t)(n0+m)*FEAT + k0 + k4);
            sA[k4+0][m]=v.x; sA[k4+1][m]=v.y; sA[k4+2][m]=v.z; sA[k4+3][m]=v.w;
        }
        for (int i = tid; i < OT_K*OT_N/4; i += 256) {
            int k = i >> 4, c4 = (i & 15) * 4;
            *(float4*)&sB[k][c4] = *(const float4*)(wo + (size_t)(k0+k)*COUT + col0 + c4);
        }
        __syncthreads();
        #pragma unroll
        for (int kk = 0; kk < OT_K; kk++) {
            float4 b = *(float4*)&sB[kk][tx*4];
            float4 a = *(float4*)&sA[kk][ty*4];
            acc[0].x += a.x*b.x; acc[0].y += a.x*b.y; acc[0].z += a.x*b.z; acc[0].w += a.x*b.w;
            acc[1].x += a.y*b.x; acc[1].y += a.y*b.y; acc[1].z += a.y*b.z; acc[1].w += a.y*b.w;
            acc[2].x += a.z*b.x; acc[2].y += a.z*b.y; acc[2].z += a.z*b.z; acc[2].w += a.z*b.w;
            acc[3].x += a.w*b.x; acc[3].y += a.w*b.y; acc[3].z += a.w*b.z; acc[3].w += a.w*b.w;
        }
        __syncthreads();
    }
    #pragma unroll
    for (int r = 0; r < 4; r++)
        *(float4*)&g_opart[sp][n0+ty*4+r][col0+tx*4] = acc[r];
}

__global__ void out_reduce_kernel(const float* __restrict__ bo,
                                  float* __restrict__ out) {
    int n = blockIdx.x, o = threadIdx.x;
    float a = bo[o];
    #pragma unroll
    for (int sp = 0; sp < SPLITS; sp++) a += g_opart[sp][n][o];
    out[(size_t)n*COUT + o] = a;
}

// ---------------- launch ---------------------------------------------------
extern "C" void kernel_launch(void* const* d_in, const int* in_sizes, int n_in,
                              void* d_out, int out_size) {
    const float* s     = (const float*)d_in[0];
    const float* z     = (const float*)d_in[1];
    const float* trans = (const float*)d_in[2];
    const float* rot   = (const float*)d_in[3];
    const int*   mask  = (const int*)  d_in[4];
    const float* wq    = (const float*)d_in[5];
    const float* bq    = (const float*)d_in[6];
    const float* wk    = (const float*)d_in[7];
    const float* bk    = (const float*)d_in[8];
    const float* wv    = (const float*)d_in[9];
    const float* bv    = (const float*)d_in[10];
    const float* wqp   = (const float*)d_in[11];
    const float* bqp   = (const float*)d_in[12];
    const float* wkp   = (const float*)d_in[13];
    const float* bkp   = (const float*)d_in[14];
    const float* wvp   = (const float*)d_in[15];
    const float* bvp   = (const float*)d_in[16];
    const float* wb    = (const float*)d_in[17];
    const float* bb    = (const float*)d_in[18];
    const float* wo    = (const float*)d_in[19];
    const float* bo    = (const float*)d_in[20];
    float* out = (float*)d_out;

    cudaFuncSetAttribute(attn_kernel,
                         cudaFuncAttributeMaxDynamicSharedMemorySize, SMEM_BYTES);

    proj_gemm_kernel<<<dim3(NN/PT_M, 24), 192>>>(s,
        wq, bq, wk, bk, wv, bv, wqp, bqp, wkp, bkp, wvp, bvp);
    rotate_points_kernel<<<NN, 192>>>(rot, trans);
    zb_gemm_kernel<<<(NN*NN)/(ZB_THREADS*ZB_ROWS), ZB_THREADS>>>(z, wb, bb);
    attn_kernel<<<NN, 384, SMEM_BYTES>>>(z, trans, rot, mask, wb, bb);
    out_gemm_kernel<<<dim3(NN/OT_M, COUT/OT_N, SPLITS), 256>>>(wo);
    out_reduce_kernel<<<NN, COUT>>>(bo, out);
}

// round 10
// speedup vs baseline: 3.7058x; 1.3581x over previous
#include <cuda_runtime.h>
#include <math.h>

// Problem constants
#define NN    512
#define CS    384
#define CZ    128
#define HH    12
#define CH    16
#define PQN   4
#define PVN   8
#define DPROJ 1152
#define FH    (CH + PVN*3 + PVN + CZ)  // 176
#define FEAT  (HH*FH)                  // 2112
#define COUT  384

// segment bases inside g_proj row
#define OFF_PQ_Q   0
#define OFF_PQ_K   192
#define OFF_PQ_V   384
#define OFF_PQ_QP  576
#define OFF_PQ_KP  720
#define OFF_PQ_VP  864

// ---------------- scratch ----------------
__device__ __align__(16) float g_proj[NN*DPROJ];
__device__ __align__(16) float g_qpg [NN*HH*PQN*3];
__device__ __align__(16) float g_kpg [NN*HH*PQN*3];
__device__ __align__(16) float g_vpg [NN*HH*PVN*3];
__device__ __align__(16) float g_feat[NN*FEAT];
__device__ __align__(16) float g_zb  [(size_t)NN*NN*HH];   // 12.6 MB
__device__ __align__(16) float g_w   [(size_t)NN*NN*HH];   // softmax weights
#define SPLITS 4
__device__ __align__(16) float g_opart[SPLITS][NN][COUT];

// =================== fused projection SGEMM ===========================
#define PT_M 64
#define PT_N 48
#define PT_K 16
__global__ void proj_gemm_kernel(const float* __restrict__ s,
    const float* __restrict__ wq,  const float* __restrict__ bq,
    const float* __restrict__ wk,  const float* __restrict__ bk,
    const float* __restrict__ wv,  const float* __restrict__ bv,
    const float* __restrict__ wqp, const float* __restrict__ bqp,
    const float* __restrict__ wkp, const float* __restrict__ bkp,
    const float* __restrict__ wvp, const float* __restrict__ bvp) {
    int bt = blockIdx.y;
    const float *W, *B; int Dout, base, t;
    if      (bt < 4)  { W=wq;  B=bq;  Dout=192; base=OFF_PQ_Q;  t=bt; }
    else if (bt < 8)  { W=wk;  B=bk;  Dout=192; base=OFF_PQ_K;  t=bt-4; }
    else if (bt < 12) { W=wv;  B=bv;  Dout=192; base=OFF_PQ_V;  t=bt-8; }
    else if (bt < 15) { W=wqp; B=bqp; Dout=144; base=OFF_PQ_QP; t=bt-12; }
    else if (bt < 18) { W=wkp; B=bkp; Dout=144; base=OFF_PQ_KP; t=bt-15; }
    else              { W=wvp; B=bvp; Dout=288; base=OFF_PQ_VP; t=bt-18; }
    int col0 = t*PT_N;
    int n0   = blockIdx.x*PT_M;

    __shared__ float sA[PT_K][PT_M];
    __shared__ float sB[PT_K][PT_N];
    int tid = threadIdx.x;           // 192
    int tx = tid % 12, ty = tid / 12;
    float4 acc[4] = {};

    for (int k0 = 0; k0 < CS; k0 += PT_K) {
        for (int i = tid; i < PT_M*PT_K/4; i += 192) {
            int m = i >> 2, k4 = (i & 3) * 4;
            float4 v = *(const float4*)(s + (size_t)(n0+m)*CS + k0 + k4);
            sA[k4+0][m]=v.x; sA[k4+1][m]=v.y; sA[k4+2][m]=v.z; sA[k4+3][m]=v.w;
        }
        for (int i = tid; i < PT_K*PT_N/4; i += 192) {
            int k = i / 12, c4 = (i % 12) * 4;
            *(float4*)&sB[k][c4] = *(const float4*)(W + (size_t)(k0+k)*Dout + col0 + c4);
        }
        __syncthreads();
        #pragma unroll
        for (int kk = 0; kk < PT_K; kk++) {
            float4 b = *(float4*)&sB[kk][tx*4];
            float4 a = *(float4*)&sA[kk][ty*4];
            acc[0].x += a.x*b.x; acc[0].y += a.x*b.y; acc[0].z += a.x*b.z; acc[0].w += a.x*b.w;
            acc[1].x += a.y*b.x; acc[1].y += a.y*b.y; acc[1].z += a.y*b.z; acc[1].w += a.y*b.w;
            acc[2].x += a.z*b.x; acc[2].y += a.z*b.y; acc[2].z += a.z*b.z; acc[2].w += a.z*b.w;
            acc[3].x += a.w*b.x; acc[3].y += a.w*b.y; acc[3].z += a.w*b.z; acc[3].w += a.w*b.w;
        }
        __syncthreads();
    }
    float4 bias4 = *(const float4*)(B + col0 + tx*4);
    #pragma unroll
    for (int r = 0; r < 4; r++) {
        float4 o = acc[r];
        o.x += bias4.x; o.y += bias4.y; o.z += bias4.z; o.w += bias4.w;
        *(float4*)(g_proj + (size_t)(n0+ty*4+r)*DPROJ + base + col0 + tx*4) = o;
    }
}

// =================== rotation epilogue for point projections ==========
__global__ void rotate_points_kernel(const float* __restrict__ rot,
                                     const float* __restrict__ trans) {
    int n = blockIdx.x, t = threadIdx.x;
    __shared__ float R[9], T[3];
    if (t < 9) R[t] = rot[n*9 + t];
    if (t < 3) T[t] = trans[n*3 + t];
    __syncthreads();
    int src_off, hp; float* dst;
    if      (t < 48)  { hp = t;      src_off = OFF_PQ_QP; dst = g_qpg + n*144; }
    else if (t < 96)  { hp = t-48;   src_off = OFF_PQ_KP; dst = g_kpg + n*144; }
    else              { hp = t-96;   src_off = OFF_PQ_VP; dst = g_vpg + n*288; }
    const float* l = g_proj + (size_t)n*DPROJ + src_off + hp*3;
    float l0=l[0], l1=l[1], l2=l[2];
    dst[hp*3+0] = R[0]*l0 + R[1]*l1 + R[2]*l2 + T[0];
    dst[hp*3+1] = R[3]*l0 + R[4]*l1 + R[5]*l2 + T[1];
    dst[hp*3+2] = R[6]*l0 + R[7]*l1 + R[8]*l2 + T[2];
}

// =================== z-bias GEMM ======================================
#define ZB_THREADS 128
#define ZB_ROWS    4
__global__ void zb_gemm_kernel(const float* __restrict__ z,
                               const float* __restrict__ wb,
                               const float* __restrict__ bb) {
    __shared__ float wb_s[CZ*HH];
    __shared__ float bb_s[HH];
    int tid = threadIdx.x;
    for (int i = tid; i < CZ*HH; i += ZB_THREADS) wb_s[i] = wb[i];
    if (tid < HH) bb_s[tid] = bb[tid];
    __syncthreads();

    size_t row0 = ((size_t)blockIdx.x*ZB_THREADS + tid) * ZB_ROWS;
    float acc[ZB_ROWS][HH];
    #pragma unroll
    for (int r = 0; r < ZB_ROWS; r++)
        #pragma unroll
        for (int h = 0; h < HH; h++) acc[r][h] = bb_s[h];

    const float* zp = z + row0*CZ;
    #pragma unroll 4
    for (int k4 = 0; k4 < CZ/4; k4++) {
        float4 zv[ZB_ROWS];
        #pragma unroll
        for (int r = 0; r < ZB_ROWS; r++)
            zv[r] = *(const float4*)(zp + (size_t)r*CZ + k4*4);
        #pragma unroll
        for (int kk = 0; kk < 4; kk++) {
            const float* wrow = wb_s + (k4*4+kk)*HH;
            #pragma unroll
            for (int h = 0; h < HH; h++) {
                float w = wrow[h];
                acc[0][h] += ((const float*)&zv[0])[kk] * w;
                acc[1][h] += ((const float*)&zv[1])[kk] * w;
                acc[2][h] += ((const float*)&zv[2])[kk] * w;
                acc[3][h] += ((const float*)&zv[3])[kk] * w;
            }
        }
    }
    float* op = g_zb + row0*HH;
    #pragma unroll
    for (int r = 0; r < ZB_ROWS; r++)
        #pragma unroll
        for (int h = 0; h < HH; h++) op[r*HH + h] = acc[r][h];
}

// =================== kernel A: logits + softmax -> g_w ================
__global__ void attn_logits_kernel(const int* __restrict__ mask) {
    __shared__ float q_s[192];
    __shared__ float qpg_s[144];
    __shared__ float logits[NN*HH];
    __shared__ float inv_dn[HH];

    int n = blockIdx.x, tid = threadIdx.x;   // 384 threads
    for (int i = tid; i < 192; i += 384) q_s[i]   = g_proj[(size_t)n*DPROJ + i];
    for (int i = tid; i < 144; i += 384) qpg_s[i] = g_qpg[n*144 + i];
    int mask_n = mask[n];
    __syncthreads();

    {
        const int ml0 = tid / HH;    // 0..31
        const int h   = tid % HH;
        float4 qv[4], qp[3];
        #pragma unroll
        for (int c = 0; c < 4; c++) qv[c] = ((const float4*)(q_s + h*CH))[c];
        #pragma unroll
        for (int c = 0; c < 3; c++) qp[c] = ((const float4*)(qpg_s + h*12))[c];

        const float* zb_n = g_zb + (size_t)n*NN*HH;
        for (int m = ml0; m < NN; m += 32) {
            const float4* kr = (const float4*)(g_proj + (size_t)m*DPROJ + OFF_PQ_K + h*CH);
            float sc = 0.f;
            #pragma unroll
            for (int c = 0; c < 4; c++) {
                float4 b = __ldg(&kr[c]);
                sc += qv[c].x*b.x + qv[c].y*b.y + qv[c].z*b.z + qv[c].w*b.w;
            }
            float logit = sc * 0.25f;
            const float4* kp = (const float4*)(g_kpg + m*144 + h*12);
            float ss = 0.f;
            #pragma unroll
            for (int c = 0; c < 3; c++) {
                float4 b = __ldg(&kp[c]);
                float dx=qp[c].x-b.x, dy=qp[c].y-b.y, dz=qp[c].z-b.z, dw=qp[c].w-b.w;
                ss += dx*dx + dy*dy + dz*dz + dw*dw;
            }
            logit -= 0.5f * ss;
            logit += __ldg(zb_n + m*HH + h);
            if (mask_n == 0 || __ldg(mask + m) == 0) logit = -1e30f;
            logits[m*HH + h] = logit;
        }
    }
    __syncthreads();

    // softmax: one warp per head
    {
        int w = tid >> 5, lane = tid & 31;
        float mx = -1e30f;
        for (int m = lane; m < NN; m += 32) mx = fmaxf(mx, logits[m*HH + w]);
        #pragma unroll
        for (int o = 16; o; o >>= 1) mx = fmaxf(mx, __shfl_xor_sync(0xffffffffu, mx, o));
        float s = 0.f;
        for (int m = lane; m < NN; m += 32) {
            float e = __expf(logits[m*HH + w] - mx);
            logits[m*HH + w] = e;
            s += e;
        }
        #pragma unroll
        for (int o = 16; o; o >>= 1) s += __shfl_xor_sync(0xffffffffu, s, o);
        if (lane == 0) inv_dn[w] = 1.f / s;
    }
    __syncthreads();

    // write normalized weights
    float* wout = g_w + (size_t)n*NN*HH;
    for (int i = tid; i < NN*HH; i += 384)
        wout[i] = logits[i] * inv_dn[i % HH];
}

// =================== kernel B: weighted sums ==========================
// 384 threads: warps 0-7 (256t) pair features over z; warps 8-11 v + vpg.
__global__ void attn_wsum_kernel(const float* __restrict__ z,
                                 const float* __restrict__ trans,
                                 const float* __restrict__ rot) {
    __shared__ __align__(16) float w_s[NN*HH];     // 24 KB
    __shared__ float acc_s[HH*168];                // 8 KB
    __shared__ float R[9], T[3];

    int n = blockIdx.x, tid = threadIdx.x;
    for (int i = tid; i < NN*HH; i += 384) w_s[i] = g_w[(size_t)n*NN*HH + i];
    for (int i = tid; i < HH*168; i += 384) acc_s[i] = 0.f;
    if (tid < 9) R[tid] = rot[n*9 + tid];
    if (tid < 3) T[tid] = trans[n*3 + tid];
    __syncthreads();

    if (tid < 256) {
        // ---- pair features: out[h, c] = sum_m w[m,h]*z[n,m,c] ----
        int c_g    = tid & 31;     // float4 channel group 0..31
        int stripe = tid >> 5;     // 0..7
        float4 acc[HH];
        #pragma unroll
        for (int h = 0; h < HH; h++) acc[h] = make_float4(0.f,0.f,0.f,0.f);

        const float4* zrow = (const float4*)(z + (size_t)n*NN*CZ);
        int mbeg = stripe*64;
        #pragma unroll 4
        for (int it = 0; it < 64; it++) {
            int m = mbeg + it;
            float4 zv = __ldg(zrow + m*32 + c_g);
            const float4* wr = (const float4*)(w_s + m*HH);
            float4 w0 = wr[0], w1 = wr[1], w2 = wr[2];
            const float* wf = (const float*)&w0;
            #pragma unroll
            for (int h = 0; h < 4; h++) {
                float wv = wf[h];
                acc[h].x += wv*zv.x; acc[h].y += wv*zv.y;
                acc[h].z += wv*zv.z; acc[h].w += wv*zv.w;
            }
            const float* wf1 = (const float*)&w1;
            #pragma unroll
            for (int h = 0; h < 4; h++) {
                float wv = wf1[h];
                acc[4+h].x += wv*zv.x; acc[4+h].y += wv*zv.y;
                acc[4+h].z += wv*zv.z; acc[4+h].w += wv*zv.w;
            }
            const float* wf2 = (const float*)&w2;
            #pragma unroll
            for (int h = 0; h < 4; h++) {
                float wv = wf2[h];
                acc[8+h].x += wv*zv.x; acc[8+h].y += wv*zv.y;
                acc[8+h].z += wv*zv.z; acc[8+h].w += wv*zv.w;
            }
        }
        // reduce 8 stripes via smem atomics (distinct addrs within warp)
        #pragma unroll
        for (int h = 0; h < HH; h++) {
            float* dst = acc_s + h*168 + 40 + c_g*4;
            atomicAdd(dst+0, acc[h].x);
            atomicAdd(dst+1, acc[h].y);
            atomicAdd(dst+2, acc[h].z);
            atomicAdd(dst+3, acc[h].w);
        }
    } else {
        // ---- v (48 groups) + vpg (72 groups): one float4 group/thread ----
        int vt = tid - 256;   // 0..127, use 0..119
        if (vt < 120) {
            const float* src; int stride, h, joff;
            if (vt < 48) {
                h = vt >> 2; int c4 = vt & 3;
                src = g_proj + OFF_PQ_V + h*CH + c4*4;
                stride = DPROJ; joff = c4*4;
            } else {
                int vt2 = vt - 48;
                h = vt2 / 6; int g = vt2 % 6;
                src = g_vpg + h*24 + g*4;
                stride = 288; joff = 16 + g*4;
            }
            const float* wcol = w_s + h;
            float4 a = make_float4(0.f,0.f,0.f,0.f);
            #pragma unroll 4
            for (int m = 0; m < NN; m++) {
                float4 xv = __ldg((const float4*)(src + (size_t)m*stride));
                float wv = wcol[m*HH];
                a.x += wv*xv.x; a.y += wv*xv.y; a.z += wv*xv.z; a.w += wv*xv.w;
            }
            *(float4*)(acc_s + h*168 + joff) = a;
        }
    }
    __syncthreads();

    // ---- finalize (w already normalized: no division) ----
    for (int s_ = tid; s_ < HH*168; s_ += 384) {
        int h = s_/168, j = s_%168;
        float val = acc_s[s_];
        if (j < 16)       g_feat[(size_t)n*FEAT + h*FH + j] = val;
        else if (j >= 40) g_feat[(size_t)n*FEAT + h*FH + 48 + (j-40)] = val;
    }
    if (tid < HH*PVN) {
        int h = tid / PVN, p = tid % PVN;
        float x0_ = acc_s[h*168 + 16 + p*3 + 0] - T[0];
        float x1_ = acc_s[h*168 + 16 + p*3 + 1] - T[1];
        float x2_ = acc_s[h*168 + 16 + p*3 + 2] - T[2];
        float l0 = R[0]*x0_ + R[3]*x1_ + R[6]*x2_;
        float l1 = R[1]*x0_ + R[4]*x1_ + R[7]*x2_;
        float l2 = R[2]*x0_ + R[5]*x1_ + R[8]*x2_;
        g_feat[(size_t)n*FEAT + h*FH + 16 + p*3 + 0] = l0;
        g_feat[(size_t)n*FEAT + h*FH + 16 + p*3 + 1] = l1;
        g_feat[(size_t)n*FEAT + h*FH + 16 + p*3 + 2] = l2;
        g_feat[(size_t)n*FEAT + h*FH + 40 + p] = sqrtf(l0*l0 + l1*l1 + l2*l2);
    }
}

// =================== output projection: split-K SGEMM ==================
#define OT_M 64
#define OT_N 64
#define OT_K 16
#define KSPLIT (FEAT/SPLITS)   // 528
__global__ void out_gemm_kernel(const float* __restrict__ wo) {
    int n0   = blockIdx.x*OT_M;
    int col0 = blockIdx.y*OT_N;
    int sp   = blockIdx.z;
    __shared__ float sA[OT_K][OT_M];
    __shared__ float sB[OT_K][OT_N];
    int tid = threadIdx.x;
    int tx = tid & 15, ty = tid >> 4;
    float4 acc[4] = {};
    int kbeg = sp*KSPLIT, kend = kbeg + KSPLIT;
    for (int k0 = kbeg; k0 < kend; k0 += OT_K) {
        for (int i = tid; i < OT_M*OT_K/4; i += 256) {
            int m = i >> 2, k4 = (i & 3) * 4;
            float4 v = *(const float4*)(g_feat + (size_t)(n0+m)*FEAT + k0 + k4);
            sA[k4+0][m]=v.x; sA[k4+1][m]=v.y; sA[k4+2][m]=v.z; sA[k4+3][m]=v.w;
        }
        for (int i = tid; i < OT_K*OT_N/4; i += 256) {
            int k = i >> 4, c4 = (i & 15) * 4;
            *(float4*)&sB[k][c4] = *(const float4*)(wo + (size_t)(k0+k)*COUT + col0 + c4);
        }
        __syncthreads();
        #pragma unroll
        for (int kk = 0; kk < OT_K; kk++) {
            float4 b = *(float4*)&sB[kk][tx*4];
            float4 a = *(float4*)&sA[kk][ty*4];
            acc[0].x += a.x*b.x; acc[0].y += a.x*b.y; acc[0].z += a.x*b.z; acc[0].w += a.x*b.w;
            acc[1].x += a.y*b.x; acc[1].y += a.y*b.y; acc[1].z += a.y*b.z; acc[1].w += a.y*b.w;
            acc[2].x += a.z*b.x; acc[2].y += a.z*b.y; acc[2].z += a.z*b.z; acc[2].w += a.z*b.w;
            acc[3].x += a.w*b.x; acc[3].y += a.w*b.y; acc[3].z += a.w*b.z; acc[3].w += a.w*b.w;
        }
        __syncthreads();
    }
    #pragma unroll
    for (int r = 0; r < 4; r++)
        *(float4*)&g_opart[sp][n0+ty*4+r][col0+tx*4] = acc[r];
}

__global__ void out_reduce_kernel(const float* __restrict__ bo,
                                  float* __restrict__ out) {
    int n = blockIdx.x, o = threadIdx.x;
    float a = bo[o];
    #pragma unroll
    for (int sp = 0; sp < SPLITS; sp++) a += g_opart[sp][n][o];
    out[(size_t)n*COUT + o] = a;
}

// ---------------- launch ---------------------------------------------------
extern "C" void kernel_launch(void* const* d_in, const int* in_sizes, int n_in,
                              void* d_out, int out_size) {
    const float* s     = (const float*)d_in[0];
    const float* z     = (const float*)d_in[1];
    const float* trans = (const float*)d_in[2];
    const float* rot   = (const float*)d_in[3];
    const int*   mask  = (const int*)  d_in[4];
    const float* wq    = (const float*)d_in[5];
    const float* bq    = (const float*)d_in[6];
    const float* wk    = (const float*)d_in[7];
    const float* bk    = (const float*)d_in[8];
    const float* wv    = (const float*)d_in[9];
    const float* bv    = (const float*)d_in[10];
    const float* wqp   = (const float*)d_in[11];
    const float* bqp   = (const float*)d_in[12];
    const float* wkp   = (const float*)d_in[13];
    const float* bkp   = (const float*)d_in[14];
    const float* wvp   = (const float*)d_in[15];
    const float* bvp   = (const float*)d_in[16];
    const float* wb    = (const float*)d_in[17];
    const float* bb    = (const float*)d_in[18];
    const float* wo    = (const float*)d_in[19];
    const float* bo    = (const float*)d_in[20];
    float* out = (float*)d_out;

    proj_gemm_kernel<<<dim3(NN/PT_M, 24), 192>>>(s,
        wq, bq, wk, bk, wv, bv, wqp, bqp, wkp, bkp, wvp, bvp);
    rotate_points_kernel<<<NN, 192>>>(rot, trans);
    zb_gemm_kernel<<<(NN*NN)/(ZB_THREADS*ZB_ROWS), ZB_THREADS>>>(z, wb, bb);
    attn_logits_kernel<<<NN, 384>>>(mask);
    attn_wsum_kernel<<<NN, 384>>>(z, trans, rot);
    out_gemm_kernel<<<dim3(NN/OT_M, COUT/OT_N, SPLITS), 256>>>(wo);
    out_reduce_kernel<<<NN, COUT>>>(bo, out);
}

// round 11
// speedup vs baseline: 4.9561x; 1.3374x over previous
#include <cuda_runtime.h>
#include <math.h>

// Problem constants
#define NN    512
#define CS    384
#define CZ    128
#define HH    12
#define CH    16
#define PQN   4
#define PVN   8
#define DPROJ 1152
#define FH    (CH + PVN*3 + PVN + CZ)  // 176
#define FEAT  (HH*FH)                  // 2112
#define COUT  384
#define DK    28                       // combined qk+point dim

// segment bases inside g_proj row
#define OFF_PQ_Q   0
#define OFF_PQ_K   192
#define OFF_PQ_V   384
#define OFF_PQ_QP  576
#define OFF_PQ_KP  720
#define OFF_PQ_VP  864

// ---------------- scratch ----------------
__device__ __align__(16) float g_proj[NN*DPROJ];
__device__ __align__(16) float g_qk  [HH*NN*DK];            // Q' = [0.25*q, qpg]
__device__ __align__(16) float g_kk  [HH*NN*DK];            // K' = [k, kpg]
__device__ __align__(16) float g_sqk [HH*NN];               // 0.5*|kpg|^2
__device__ __align__(16) float g_vpg [NN*HH*PVN*3];
__device__ __align__(16) float g_feat[NN*FEAT];
__device__ __align__(16) float g_zb  [(size_t)HH*NN*NN];    // [h][n][m]
__device__ __align__(16) float g_att [(size_t)HH*NN*NN];    // logits -> weights
#define SPLITS 6
__device__ __align__(16) float g_opart[SPLITS][NN][COUT];

// =================== fused projection SGEMM ===========================
#define PT_M 64
#define PT_N 48
#define PT_K 16
__global__ void proj_gemm_kernel(const float* __restrict__ s,
    const float* __restrict__ wq,  const float* __restrict__ bq,
    const float* __restrict__ wk,  const float* __restrict__ bk,
    const float* __restrict__ wv,  const float* __restrict__ bv,
    const float* __restrict__ wqp, const float* __restrict__ bqp,
    const float* __restrict__ wkp, const float* __restrict__ bkp,
    const float* __restrict__ wvp, const float* __restrict__ bvp) {
    int bt = blockIdx.y;
    const float *W, *B; int Dout, base, t;
    if      (bt < 4)  { W=wq;  B=bq;  Dout=192; base=OFF_PQ_Q;  t=bt; }
    else if (bt < 8)  { W=wk;  B=bk;  Dout=192; base=OFF_PQ_K;  t=bt-4; }
    else if (bt < 12) { W=wv;  B=bv;  Dout=192; base=OFF_PQ_V;  t=bt-8; }
    else if (bt < 15) { W=wqp; B=bqp; Dout=144; base=OFF_PQ_QP; t=bt-12; }
    else if (bt < 18) { W=wkp; B=bkp; Dout=144; base=OFF_PQ_KP; t=bt-15; }
    else              { W=wvp; B=bvp; Dout=288; base=OFF_PQ_VP; t=bt-18; }
    int col0 = t*PT_N;
    int n0   = blockIdx.x*PT_M;

    __shared__ float sA[PT_K][PT_M];
    __shared__ float sB[PT_K][PT_N];
    int tid = threadIdx.x;           // 192
    int tx = tid % 12, ty = tid / 12;
    float4 acc[4] = {};

    for (int k0 = 0; k0 < CS; k0 += PT_K) {
        for (int i = tid; i < PT_M*PT_K/4; i += 192) {
            int m = i >> 2, k4 = (i & 3) * 4;
            float4 v = *(const float4*)(s + (size_t)(n0+m)*CS + k0 + k4);
            sA[k4+0][m]=v.x; sA[k4+1][m]=v.y; sA[k4+2][m]=v.z; sA[k4+3][m]=v.w;
        }
        for (int i = tid; i < PT_K*PT_N/4; i += 192) {
            int k = i / 12, c4 = (i % 12) * 4;
            *(float4*)&sB[k][c4] = *(const float4*)(W + (size_t)(k0+k)*Dout + col0 + c4);
        }
        __syncthreads();
        #pragma unroll
        for (int kk = 0; kk < PT_K; kk++) {
            float4 b = *(float4*)&sB[kk][tx*4];
            float4 a = *(float4*)&sA[kk][ty*4];
            acc[0].x += a.x*b.x; acc[0].y += a.x*b.y; acc[0].z += a.x*b.z; acc[0].w += a.x*b.w;
            acc[1].x += a.y*b.x; acc[1].y += a.y*b.y; acc[1].z += a.y*b.z; acc[1].w += a.y*b.w;
            acc[2].x += a.z*b.x; acc[2].y += a.z*b.y; acc[2].z += a.z*b.z; acc[2].w += a.z*b.w;
            acc[3].x += a.w*b.x; acc[3].y += a.w*b.y; acc[3].z += a.w*b.z; acc[3].w += a.w*b.w;
        }
        __syncthreads();
    }
    float4 bias4 = *(const float4*)(B + col0 + tx*4);
    #pragma unroll
    for (int r = 0; r < 4; r++) {
        float4 o = acc[r];
        o.x += bias4.x; o.y += bias4.y; o.z += bias4.z; o.w += bias4.w;
        *(float4*)(g_proj + (size_t)(n0+ty*4+r)*DPROJ + base + col0 + tx*4) = o;
    }
}

// =================== prep: rotate points, build Q'/K'/sqk/vpg =========
__global__ void prep_kernel(const float* __restrict__ rot,
                            const float* __restrict__ trans) {
    int n = blockIdx.x, t = threadIdx.x;   // 192 threads
    __shared__ float R[9], T[3];
    __shared__ float kpg_s[144];
    if (t < 9) R[t] = rot[n*9 + t];
    if (t < 3) T[t] = trans[n*3 + t];
    __syncthreads();

    // q/k scalar parts
    {
        int h = t / 16, c = t % 16;
        g_qk[(size_t)h*NN*DK + n*DK + c] = g_proj[(size_t)n*DPROJ + t] * 0.25f;
        g_kk[(size_t)h*NN*DK + n*DK + c] = g_proj[(size_t)n*DPROJ + 192 + t];
    }
    // points
    if (t < 48) {               // qp
        const float* l = g_proj + (size_t)n*DPROJ + OFF_PQ_QP + t*3;
        float l0=l[0], l1=l[1], l2=l[2];
        int h = t/4, p = t%4;
        float* dst = g_qk + (size_t)h*NN*DK + n*DK + 16 + p*3;
        dst[0] = R[0]*l0 + R[1]*l1 + R[2]*l2 + T[0];
        dst[1] = R[3]*l0 + R[4]*l1 + R[5]*l2 + T[1];
        dst[2] = R[6]*l0 + R[7]*l1 + R[8]*l2 + T[2];
    } else if (t < 96) {        // kp
        int tt = t - 48;
        const float* l = g_proj + (size_t)n*DPROJ + OFF_PQ_KP + tt*3;
        float l0=l[0], l1=l[1], l2=l[2];
        int h = tt/4, p = tt%4;
        float g0 = R[0]*l0 + R[1]*l1 + R[2]*l2 + T[0];
        float g1 = R[3]*l0 + R[4]*l1 + R[5]*l2 + T[1];
        float g2 = R[6]*l0 + R[7]*l1 + R[8]*l2 + T[2];
        float* dst = g_kk + (size_t)h*NN*DK + n*DK + 16 + p*3;
        dst[0]=g0; dst[1]=g1; dst[2]=g2;
        kpg_s[tt*3+0]=g0; kpg_s[tt*3+1]=g1; kpg_s[tt*3+2]=g2;
    } else {                    // vp
        int tt = t - 96;
        const float* l = g_proj + (size_t)n*DPROJ + OFF_PQ_VP + tt*3;
        float l0=l[0], l1=l[1], l2=l[2];
        float* dst = g_vpg + (size_t)n*288 + tt*3;
        dst[0] = R[0]*l0 + R[1]*l1 + R[2]*l2 + T[0];
        dst[1] = R[3]*l0 + R[4]*l1 + R[5]*l2 + T[1];
        dst[2] = R[6]*l0 + R[7]*l1 + R[8]*l2 + T[2];
    }
    __syncthreads();
    if (t < HH) {
        float s = 0.f;
        #pragma unroll
        for (int j = 0; j < 12; j++) { float v = kpg_s[t*12 + j]; s += v*v; }
        g_sqk[t*NN + n] = 0.5f * s;
    }
}

// =================== zb GEMM: smem-staged, one block per n ============
// zb[h][n][m] = z[n,m,:] @ wb[:,h]   (bb dropped: softmax-shift invariant)
#define ZKC 16
__global__ void zb_gemm_kernel(const float* __restrict__ z,
                               const float* __restrict__ wb) {
    __shared__ float z_s[NN*(ZKC+1)];    // 512 x 17 = 34.8 KB
    __shared__ float wb_s[CZ*HH];        // [k][h]
    int n = blockIdx.x, tid = threadIdx.x;   // 128 threads
    for (int i = tid; i < CZ*HH; i += 128) wb_s[i] = wb[i];

    float acc[4][HH] = {};
    const float* zrow = z + (size_t)n*NN*CZ;

    for (int c = 0; c < CZ/ZKC; c++) {
        __syncthreads();
        // stage z[512][16] coalesced
        for (int i = tid; i < NN*ZKC/4; i += 128) {
            int row = i >> 2, c4 = (i & 3) * 4;
            float4 v = *(const float4*)(zrow + (size_t)row*CZ + c*ZKC + c4);
            float* d = z_s + row*(ZKC+1) + c4;
            d[0]=v.x; d[1]=v.y; d[2]=v.z; d[3]=v.w;
        }
        __syncthreads();
        #pragma unroll
        for (int k = 0; k < ZKC; k++) {
            const float* wrow = wb_s + (c*ZKC + k)*HH;
            float zv[4];
            #pragma unroll
            for (int r = 0; r < 4; r++) zv[r] = z_s[(tid + 128*r)*(ZKC+1) + k];
            #pragma unroll
            for (int h = 0; h < HH; h++) {
                float w = wrow[h];
                acc[0][h] += zv[0]*w;
                acc[1][h] += zv[1]*w;
                acc[2][h] += zv[2]*w;
                acc[3][h] += zv[3]*w;
            }
        }
    }
    // write [h][n][m]: per h-plane, warp lanes cover consecutive m
    #pragma unroll
    for (int h = 0; h < HH; h++) {
        float* dst = g_zb + (size_t)h*NN*NN + (size_t)n*NN;
        #pragma unroll
        for (int r = 0; r < 4; r++) dst[tid + 128*r] = acc[r][h];
    }
}

// =================== logits GEMM: per-head 64x64x28 + epilogue ========
// L[h][n][m] = Q'[h][n]·K'[h][m] + zb[h][n][m] - sqk[h][m]  (masked)
__global__ void logits_gemm_kernel(const int* __restrict__ mask) {
    int m0 = blockIdx.x*64, n0 = blockIdx.y*64, h = blockIdx.z;
    __shared__ float Qs[DK][64];
    __shared__ float Ks[DK][64];
    int tid = threadIdx.x;   // 256
    int tx = tid & 15, ty = tid >> 4;

    const float4* qsrc = (const float4*)(g_qk + (size_t)h*NN*DK + (size_t)n0*DK);
    const float4* ksrc = (const float4*)(g_kk + (size_t)h*NN*DK + (size_t)m0*DK);
    for (int i = tid; i < 64*7; i += 256) {
        int row = i / 7, q = i % 7;
        float4 v = qsrc[row*7 + q];
        Qs[q*4+0][row]=v.x; Qs[q*4+1][row]=v.y; Qs[q*4+2][row]=v.z; Qs[q*4+3][row]=v.w;
        float4 w = ksrc[row*7 + q];
        Ks[q*4+0][row]=w.x; Ks[q*4+1][row]=w.y; Ks[q*4+2][row]=w.z; Ks[q*4+3][row]=w.w;
    }
    __syncthreads();

    float4 acc[4] = {};
    #pragma unroll
    for (int k = 0; k < DK; k++) {
        float4 b = *(float4*)&Ks[k][tx*4];
        float4 a = *(float4*)&Qs[k][ty*4];
        acc[0].x += a.x*b.x; acc[0].y += a.x*b.y; acc[0].z += a.x*b.z; acc[0].w += a.x*b.w;
        acc[1].x += a.y*b.x; acc[1].y += a.y*b.y; acc[1].z += a.y*b.z; acc[1].w += a.y*b.w;
        acc[2].x += a.z*b.x; acc[2].y += a.z*b.y; acc[2].z += a.z*b.z; acc[2].w += a.z*b.w;
        acc[3].x += a.w*b.x; acc[3].y += a.w*b.y; acc[3].z += a.w*b.z; acc[3].w += a.w*b.w;
    }

    float4 sq = *(const float4*)(g_sqk + h*NN + m0 + tx*4);
    int4 mm = *(const int4*)(mask + m0 + tx*4);
    #pragma unroll
    for (int r = 0; r < 4; r++) {
        int row = n0 + ty*4 + r;
        int mn = __ldg(mask + row);
        float4 zbv = *(const float4*)(g_zb + (size_t)h*NN*NN + (size_t)row*NN + m0 + tx*4);
        float4 o;
        o.x = acc[r].x + zbv.x - sq.x;
        o.y = acc[r].y + zbv.y - sq.y;
        o.z = acc[r].z + zbv.z - sq.z;
        o.w = acc[r].w + zbv.w - sq.w;
        if (mn == 0) { o.x=o.y=o.z=o.w=-1e30f; }
        else {
            if (mm.x == 0) o.x = -1e30f;
            if (mm.y == 0) o.y = -1e30f;
            if (mm.z == 0) o.z = -1e30f;
            if (mm.w == 0) o.w = -1e30f;
        }
        *(float4*)(g_att + (size_t)h*NN*NN + (size_t)row*NN + m0 + tx*4) = o;
    }
}

// =================== softmax over m (in place, normalized) ============
__global__ void softmax_kernel() {
    int n = blockIdx.x, h = blockIdx.y;
    float* row = g_att + (size_t)h*NN*NN + (size_t)n*NN;
    int tid = threadIdx.x;   // 128
    __shared__ float red[4];

    float4 v = ((float4*)row)[tid];
    float mx = fmaxf(fmaxf(v.x, v.y), fmaxf(v.z, v.w));
    #pragma unroll
    for (int o = 16; o; o >>= 1) mx = fmaxf(mx, __shfl_xor_sync(0xffffffffu, mx, o));
    if ((tid & 31) == 0) red[tid >> 5] = mx;
    __syncthreads();
    mx = fmaxf(fmaxf(red[0], red[1]), fmaxf(red[2], red[3]));

    v.x = __expf(v.x - mx); v.y = __expf(v.y - mx);
    v.z = __expf(v.z - mx); v.w = __expf(v.w - mx);
    float s = v.x + v.y + v.z + v.w;
    #pragma unroll
    for (int o = 16; o; o >>= 1) s += __shfl_xor_sync(0xffffffffu, s, o);
    __syncthreads();
    if ((tid & 31) == 0) red[tid >> 5] = s;
    __syncthreads();
    s = red[0] + red[1] + red[2] + red[3];
    float inv = 1.f / s;
    v.x *= inv; v.y *= inv; v.z *= inv; v.w *= inv;
    ((float4*)row)[tid] = v;
}

// =================== weighted sums ====================================
__global__ void attn_wsum_kernel(const float* __restrict__ z,
                                 const float* __restrict__ trans,
                                 const float* __restrict__ rot) {
    __shared__ __align__(16) float w_s[NN*HH];     // [m][h], 24 KB
    __shared__ float acc_s[HH*168];
    __shared__ float R[9], T[3];

    int n = blockIdx.x, tid = threadIdx.x;   // 384
    #pragma unroll
    for (int h = 0; h < HH; h++) {
        const float* src = g_att + (size_t)h*NN*NN + (size_t)n*NN;
        for (int i = tid; i < NN; i += 384) w_s[i*HH + h] = src[i];
    }
    for (int i = tid; i < HH*168; i += 384) acc_s[i] = 0.f;
    if (tid < 9) R[tid] = rot[n*9 + tid];
    if (tid < 3) T[tid] = trans[n*3 + tid];
    __syncthreads();

    if (tid < 256) {
        // pair features
        int c_g    = tid & 31;
        int stripe = tid >> 5;
        float4 acc[HH];
        #pragma unroll
        for (int h = 0; h < HH; h++) acc[h] = make_float4(0.f,0.f,0.f,0.f);

        const float4* zrow = (const float4*)(z + (size_t)n*NN*CZ);
        int mbeg = stripe*64;
        #pragma unroll 4
        for (int it = 0; it < 64; it++) {
            int m = mbeg + it;
            float4 zv = __ldg(zrow + m*32 + c_g);
            const float4* wr = (const float4*)(w_s + m*HH);
            float4 w0 = wr[0], w1 = wr[1], w2 = wr[2];
            const float* wf = (const float*)&w0;
            #pragma unroll
            for (int h = 0; h < 4; h++) {
                float wv = wf[h];
                acc[h].x += wv*zv.x; acc[h].y += wv*zv.y;
                acc[h].z += wv*zv.z; acc[h].w += wv*zv.w;
            }
            const float* wf1 = (const float*)&w1;
            #pragma unroll
            for (int h = 0; h < 4; h++) {
                float wv = wf1[h];
                acc[4+h].x += wv*zv.x; acc[4+h].y += wv*zv.y;
                acc[4+h].z += wv*zv.z; acc[4+h].w += wv*zv.w;
            }
            const float* wf2 = (const float*)&w2;
            #pragma unroll
            for (int h = 0; h < 4; h++) {
                float wv = wf2[h];
                acc[8+h].x += wv*zv.x; acc[8+h].y += wv*zv.y;
                acc[8+h].z += wv*zv.z; acc[8+h].w += wv*zv.w;
            }
        }
        #pragma unroll
        for (int h = 0; h < HH; h++) {
            float* dst = acc_s + h*168 + 40 + c_g*4;
            atomicAdd(dst+0, acc[h].x);
            atomicAdd(dst+1, acc[h].y);
            atomicAdd(dst+2, acc[h].z);
            atomicAdd(dst+3, acc[h].w);
        }
    } else {
        int vt = tid - 256;
        if (vt < 120) {
            const float* src; int stride, h, joff;
            if (vt < 48) {
                h = vt >> 2; int c4 = vt & 3;
                src = g_proj + OFF_PQ_V + h*CH + c4*4;
                stride = DPROJ; joff = c4*4;
            } else {
                int vt2 = vt - 48;
                h = vt2 / 6; int g = vt2 % 6;
                src = g_vpg + h*24 + g*4;
                stride = 288; joff = 16 + g*4;
            }
            const float* wcol = w_s + h;
            float4 a = make_float4(0.f,0.f,0.f,0.f);
            #pragma unroll 4
            for (int m = 0; m < NN; m++) {
                float4 xv = __ldg((const float4*)(src + (size_t)m*stride));
                float wv = wcol[m*HH];
                a.x += wv*xv.x; a.y += wv*xv.y; a.z += wv*xv.z; a.w += wv*xv.w;
            }
            *(float4*)(acc_s + h*168 + joff) = a;
        }
    }
    __syncthreads();

    for (int s_ = tid; s_ < HH*168; s_ += 384) {
        int h = s_/168, j = s_%168;
        float val = acc_s[s_];
        if (j < 16)       g_feat[(size_t)n*FEAT + h*FH + j] = val;
        else if (j >= 40) g_feat[(size_t)n*FEAT + h*FH + 48 + (j-40)] = val;
    }
    if (tid < HH*PVN) {
        int h = tid / PVN, p = tid % PVN;
        float x0_ = acc_s[h*168 + 16 + p*3 + 0] - T[0];
        float x1_ = acc_s[h*168 + 16 + p*3 + 1] - T[1];
        float x2_ = acc_s[h*168 + 16 + p*3 + 2] - T[2];
        float l0 = R[0]*x0_ + R[3]*x1_ + R[6]*x2_;
        float l1 = R[1]*x0_ + R[4]*x1_ + R[7]*x2_;
        float l2 = R[2]*x0_ + R[5]*x1_ + R[8]*x2_;
        g_feat[(size_t)n*FEAT + h*FH + 16 + p*3 + 0] = l0;
        g_feat[(size_t)n*FEAT + h*FH + 16 + p*3 + 1] = l1;
        g_feat[(size_t)n*FEAT + h*FH + 16 + p*3 + 2] = l2;
        g_feat[(size_t)n*FEAT + h*FH + 40 + p] = sqrtf(l0*l0 + l1*l1 + l2*l2);
    }
}

// =================== output projection: split-K, 8x4 micro ============
#define OT_M 128
#define OT_N 64
#define OT_K 16
#define KSPLIT (FEAT/SPLITS)   // 352
__global__ void out_gemm_kernel(const float* __restrict__ wo) {
    int n0   = blockIdx.x*OT_M;
    int col0 = blockIdx.y*OT_N;
    int sp   = blockIdx.z;
    __shared__ float sA[OT_K][OT_M];
    __shared__ float sB[OT_K][OT_N];
    int tid = threadIdx.x;   // 256
    int tx = tid & 15, ty = tid >> 4;
    float4 acc[8] = {};   // [row r: 8][col quad]
    int kbeg = sp*KSPLIT, kend = kbeg + KSPLIT;
    for (int k0 = kbeg; k0 < kend; k0 += OT_K) {
        for (int i = tid; i < OT_M*OT_K/4; i += 256) {
            int m = i >> 2, k4 = (i & 3) * 4;
            float4 v = *(const float4*)(g_feat + (size_t)(n0+m)*FEAT + k0 + k4);
            sA[k4+0][m]=v.x; sA[k4+1][m]=v.y; sA[k4+2][m]=v.z; sA[k4+3][m]=v.w;
        }
        {
            int k = tid >> 4, c4 = (tid & 15) * 4;
            *(float4*)&sB[k][c4] = *(const float4*)(wo + (size_t)(k0+k)*COUT + col0 + c4);
        }
        __syncthreads();
        #pragma unroll
        for (int kk = 0; kk < OT_K; kk++) {
            float4 b  = *(float4*)&sB[kk][tx*4];
            float4 a0 = *(float4*)&sA[kk][ty*8];
            float4 a1 = *(float4*)&sA[kk][ty*8+4];
            const float* af0 = (const float*)&a0;
            const float* af1 = (const float*)&a1;
            #pragma unroll
            for (int r = 0; r < 4; r++) {
                float av = af0[r];
                acc[r].x += av*b.x; acc[r].y += av*b.y; acc[r].z += av*b.z; acc[r].w += av*b.w;
            }
            #pragma unroll
            for (int r = 0; r < 4; r++) {
                float av = af1[r];
                acc[4+r].x += av*b.x; acc[4+r].y += av*b.y; acc[4+r].z += av*b.z; acc[4+r].w += av*b.w;
            }
        }
        __syncthreads();
    }
    #pragma unroll
    for (int r = 0; r < 8; r++)
        *(float4*)&g_opart[sp][n0+ty*8+r][col0+tx*4] = acc[r];
}

__global__ void out_reduce_kernel(const float* __restrict__ bo,
                                  float* __restrict__ out) {
    int n = blockIdx.x, o = threadIdx.x;
    float a = bo[o];
    #pragma unroll
    for (int sp = 0; sp < SPLITS; sp++) a += g_opart[sp][n][o];
    out[(size_t)n*COUT + o] = a;
}

// ---------------- launch ---------------------------------------------------
extern "C" void kernel_launch(void* const* d_in, const int* in_sizes, int n_in,
                              void* d_out, int out_size) {
    const float* s     = (const float*)d_in[0];
    const float* z     = (const float*)d_in[1];
    const float* trans = (const float*)d_in[2];
    const float* rot   = (const float*)d_in[3];
    const int*   mask  = (const int*)  d_in[4];
    const float* wq    = (const float*)d_in[5];
    const float* bq    = (const float*)d_in[6];
    const float* wk    = (const float*)d_in[7];
    const float* bk    = (const float*)d_in[8];
    const float* wv    = (const float*)d_in[9];
    const float* bv    = (const float*)d_in[10];
    const float* wqp   = (const float*)d_in[11];
    const float* bqp   = (const float*)d_in[12];
    const float* wkp   = (const float*)d_in[13];
    const float* bkp   = (const float*)d_in[14];
    const float* wvp   = (const float*)d_in[15];
    const float* bvp   = (const float*)d_in[16];
    const float* wb    = (const float*)d_in[17];
    const float* bb    = (const float*)d_in[18];
    const float* wo    = (const float*)d_in[19];
    const float* bo    = (const float*)d_in[20];
    float* out = (float*)d_out;
    (void)bb;  // bb cancels in softmax

    zb_gemm_kernel<<<NN, 128>>>(z, wb);
    proj_gemm_kernel<<<dim3(NN/PT_M, 24), 192>>>(s,
        wq, bq, wk, bk, wv, bv, wqp, bqp, wkp, bkp, wvp, bvp);
    prep_kernel<<<NN, 192>>>(rot, trans);
    logits_gemm_kernel<<<dim3(8, 8, HH), 256>>>(mask);
    softmax_kernel<<<dim3(NN, HH), 128>>>();
    attn_wsum_kernel<<<NN, 384>>>(z, trans, rot);
    out_gemm_kernel<<<dim3(NN/OT_M, COUT/OT_N, SPLITS), 256>>>(wo);
    out_reduce_kernel<<<NN, COUT>>>(bo, out);
}